// round 6
// baseline (speedup 1.0000x reference)
#include <cuda_runtime.h>
#include <cstdint>

#define BB 16
#define TT 4000
#define DD 512
#define BT (BB*TT)
#define NEG_INF (-3.4028234663852886e+38f)
#define EPSF 1e-6f

// ---------------- scratch (device globals; no allocation) ----------------
__device__ float g_qb_mono[BB][DD];
__device__ float g_qb_chunk[BB][DD];
__device__ float g_vm[DD];
__device__ float g_emono[BT];
__device__ float g_echunk[BT];
__device__ float g_alpha[BT];
__device__ float g_beta[BT];

// ---------------- JAX threefry2x32 (partitionable path) + XLA erfinv ----------------
__device__ __forceinline__ uint32_t rotl32(uint32_t x, uint32_t r) {
    return (x << r) | (x >> (32u - r));
}

__device__ __forceinline__ float erfinv_xla(float x) {
    // XLA ErfInv f32 (Giles polynomial), matches reference math
    float w = -log1pf(-x * x);
    float p;
    if (w < 5.0f) {
        w = w - 2.5f;
        p = 2.81022636e-08f;
        p = fmaf(p, w, 3.43273939e-07f);
        p = fmaf(p, w, -3.5233877e-06f);
        p = fmaf(p, w, -4.39150654e-06f);
        p = fmaf(p, w, 0.00021858087f);
        p = fmaf(p, w, -0.00125372503f);
        p = fmaf(p, w, -0.00417768164f);
        p = fmaf(p, w, 0.246640727f);
        p = fmaf(p, w, 1.50140941f);
    } else {
        w = sqrtf(w) - 3.0f;
        p = -0.000200214257f;
        p = fmaf(p, w, 0.000100950558f);
        p = fmaf(p, w, 0.00134934322f);
        p = fmaf(p, w, -0.00367342844f);
        p = fmaf(p, w, 0.00573950773f);
        p = fmaf(p, w, -0.0076224613f);
        p = fmaf(p, w, 0.00943887047f);
        p = fmaf(p, w, 1.00167406f);
        p = fmaf(p, w, 2.83297682f);
    }
    return p * x;
}

// noise[i] for flattened index i in [0, 64000), key = jax.random.key(123)
// JAX >= 0.4.36 default: jax_threefry_partitionable=True
//   counts = iota(uint64); lanes (hi, lo) = (0, i); out32 = bits1 ^ bits2
__device__ float jax_normal_123(int i) {
    const uint32_t k0 = 0u, k1 = 123u;
    const uint32_t k2 = k0 ^ k1 ^ 0x1BD11BDAu;
    uint32_t x0 = k0;                   // counts_hi (=0) + ks[0]
    uint32_t x1 = (uint32_t)i + k1;     // counts_lo (=i) + ks[1]

    // 5 groups of 4 rounds; rotation sets alternate
    #pragma unroll
    for (int r = 0; r < 4; r++) { const uint32_t ra[4] = {13,15,26,6};
        x0 += x1; x1 = rotl32(x1, ra[r]); x1 ^= x0; }
    x0 += k1; x1 += k2 + 1u;
    #pragma unroll
    for (int r = 0; r < 4; r++) { const uint32_t rb[4] = {17,29,16,24};
        x0 += x1; x1 = rotl32(x1, rb[r]); x1 ^= x0; }
    x0 += k2; x1 += k0 + 2u;
    #pragma unroll
    for (int r = 0; r < 4; r++) { const uint32_t ra[4] = {13,15,26,6};
        x0 += x1; x1 = rotl32(x1, ra[r]); x1 ^= x0; }
    x0 += k0; x1 += k1 + 3u;
    #pragma unroll
    for (int r = 0; r < 4; r++) { const uint32_t rb[4] = {17,29,16,24};
        x0 += x1; x1 = rotl32(x1, rb[r]); x1 ^= x0; }
    x0 += k1; x1 += k2 + 4u;
    #pragma unroll
    for (int r = 0; r < 4; r++) { const uint32_t ra[4] = {13,15,26,6};
        x0 += x1; x1 = rotl32(x1, ra[r]); x1 ^= x0; }
    x0 += k2; x1 += k0 + 5u;

    uint32_t bits = x0 ^ x1;            // partitionable 32-bit fold
    float f = __uint_as_float((bits >> 9) | 0x3f800000u) - 1.0f;  // [0,1)
    const float lo = -0.99999994f;                 // nextafter(-1, 0) in f32
    float scale = __fsub_rn(1.0f, lo);             // == 2.0f in f32, as XLA folds it
    float u = __fadd_rn(__fmul_rn(f, scale), lo);
    u = fmaxf(lo, u);
    return 1.41421356237f * erfinv_xla(u);         // NOISE_STD = 1
}

// ---------------- kernel 0: prep ----------------
// blocks 0..15: qb_mono[b]; 16..31: qb_chunk[b]; 32: v-norm; 33..: zeroing
__global__ void prep_kernel(const float* __restrict__ query,
                            const float* __restrict__ wqm, const float* __restrict__ bkm,
                            const float* __restrict__ wqc, const float* __restrict__ bkc,
                            const float* __restrict__ vmono, const float* __restrict__ gmono,
                            float* __restrict__ out_cv) {
    int blk = blockIdx.x, tid = threadIdx.x;  // 512 threads
    if (blk < 32) {
        int mat = blk >> 4, b = blk & 15;
        const float* wq   = mat ? wqc : wqm;
        const float* bias = mat ? bkc : bkm;
        const float* q = query + b * DD;
        float s = bias[tid];
        for (int k = 0; k < DD; k++) s = fmaf(q[k], wq[k * DD + tid], s);
        if (mat) g_qb_chunk[b][tid] = s; else g_qb_mono[b][tid] = s;
    } else if (blk == 32) {
        __shared__ float red[512];
        float v = vmono[tid];
        red[tid] = v * v;
        __syncthreads();
        for (int off = 256; off > 0; off >>= 1) {
            if (tid < off) red[tid] += red[tid + off];
            __syncthreads();
        }
        float nrm = sqrtf(red[0]);
        g_vm[tid] = gmono[0] * vmono[tid] / nrm;
    } else {
        int nb = gridDim.x - 33, bi = blk - 33;
        for (int i = bi * 512 + tid; i < 2 * BT; i += nb * 512) {
            if (i < BT) g_emono[i] = 0.f; else g_echunk[i - BT] = 0.f;
        }
        for (int i = bi * 512 + tid; i < BB * DD; i += nb * 512) out_cv[i] = 0.f;
    }
}

// ---------------- kernel 1: fused energy GEMM ----------------
// grid (8 colchunks, 500 rowblocks), 256 threads, tile 128M x 128N, K-block 32
__global__ __launch_bounds__(256, 2) void energy_kernel(
    const float* __restrict__ key, const float* __restrict__ wm,
    const float* __restrict__ wc,  const float* __restrict__ vchunk) {
    __shared__ float As[128][33];                 // [m][kk], padded
    __shared__ __align__(16) float Bs[32][128];   // [kk][n]
    int tid = threadIdx.x;
    int tx = tid & 15, ty = tid >> 4;
    int row0 = blockIdx.y * 128;
    int cc = blockIdx.x;
    int mat = cc >> 2;
    int a0 = (cc & 3) * 128;
    const float* W = mat ? wc : wm;

    float acc[8][8];
    #pragma unroll
    for (int i = 0; i < 8; i++)
        #pragma unroll
        for (int j = 0; j < 8; j++) acc[i][j] = 0.f;

    for (int kb = 0; kb < 16; kb++) {
        int kbase = kb * 32;
        __syncthreads();
        #pragma unroll
        for (int p = 0; p < 16; p++) {
            int idx = tid + p * 256;
            int kk = idx & 31, m = idx >> 5;
            As[m][kk] = fmaxf(key[(row0 + m) * 512 + kbase + kk], 0.f);  // relu
        }
        #pragma unroll
        for (int p = 0; p < 16; p++) {
            int idx = tid + p * 256;
            int n = idx & 127, kk = idx >> 7;
            Bs[kk][n] = W[(kbase + kk) * 512 + a0 + n];
        }
        __syncthreads();
        #pragma unroll 8
        for (int kk = 0; kk < 32; kk++) {
            float a[8], bf[8];
            #pragma unroll
            for (int i = 0; i < 4; i++) {
                a[i]     = As[ty * 4 + i][kk];
                a[i + 4] = As[64 + ty * 4 + i][kk];
            }
            float4 b0 = *(const float4*)&Bs[kk][tx * 4];
            float4 b1 = *(const float4*)&Bs[kk][64 + tx * 4];
            bf[0] = b0.x; bf[1] = b0.y; bf[2] = b0.z; bf[3] = b0.w;
            bf[4] = b1.x; bf[5] = b1.y; bf[6] = b1.z; bf[7] = b1.w;
            #pragma unroll
            for (int i = 0; i < 8; i++)
                #pragma unroll
                for (int j = 0; j < 8; j++)
                    acc[i][j] = fmaf(a[i], bf[j], acc[i][j]);
        }
    }
    __syncthreads();

    // epilogue: e_partial(row) = sum_a tanh(acc + qb[b][a]) * v[a]
    const float* qbp = mat ? &g_qb_chunk[0][0] : &g_qb_mono[0][0];
    const float* vp  = mat ? vchunk : g_vm;
    float* eout      = mat ? g_echunk : g_emono;
    float* red = &As[0][0];  // reuse as [128][17]
    #pragma unroll
    for (int i = 0; i < 8; i++) {
        int lr = (i < 4) ? (ty * 4 + i) : (64 + ty * 4 + i - 4);
        int gm = row0 + lr;
        int b = gm / TT;
        const float* qb = qbp + b * DD + a0;
        float s = 0.f;
        #pragma unroll
        for (int j = 0; j < 8; j++) {
            int n = (j < 4) ? (tx * 4 + j) : (64 + tx * 4 + j - 4);
            s = fmaf(tanhf(acc[i][j] + qb[n]), vp[a0 + n], s);
        }
        red[lr * 17 + tx] = s;
    }
    __syncthreads();
    if (tid < 128) {
        float s = 0.f;
        #pragma unroll
        for (int x = 0; x < 16; x++) s += red[tid * 17 + x];
        atomicAdd(&eout[row0 + tid], s);
    }
}

// ---------------- kernel 2: noise + p + alpha scan ----------------
__global__ void mono_scan_kernel(const int* __restrict__ mask,
                                 const float* __restrict__ rmono,
                                 float* __restrict__ out_alpha) {
    int b = blockIdx.x, tid = threadIdx.x;  // 128 threads
    __shared__ float lp[TT];
    __shared__ float pp[TT];
    __shared__ float partial[129];
    float r = rmono[0];
    const int CH = (TT + 127) / 128;  // 32
    int t0 = tid * CH, t1 = min(t0 + CH, TT);
    float s = 0.f;
    for (int t = t0; t < t1; t++) {
        int i = b * TT + t;
        float e = g_emono[i] + r;
        if (mask[i] == 0) e = NEG_INF;
        float x = e + jax_normal_123(i);
        float p = 1.f / (1.f + expf(-x));
        float l = logf(fminf(fmaxf(1.f - p, EPSF), 1.f));
        pp[t] = p; lp[t] = l; s += l;
    }
    partial[tid] = s;
    __syncthreads();
    if (tid == 0) {
        float run = 0.f;
        for (int i = 0; i < 128; i++) { float v = partial[i]; partial[i] = run; run += v; }
    }
    __syncthreads();
    float run = partial[tid];
    for (int t = t0; t < t1; t++) {
        float al = pp[t] * expf(run);   // exclusive cumsum -> cumprod
        run += lp[t];
        g_alpha[b * TT + t] = al;
        out_alpha[b * TT + t] = al;
    }
}

// ---------------- kernel 3: chunk energies -> beta ----------------
__global__ void chunk_post_kernel(const int* __restrict__ mask) {
    int b = blockIdx.x, tid = threadIdx.x;  // 256 threads
    __shared__ float se[TT];     // softmax_exp
    __shared__ float pref[TT];   // inclusive prefix of se
    __shared__ float qp[TT];     // q, then inclusive prefix of q
    __shared__ float sh[257];

    // masked e + block max
    float mx = -3.4e38f;
    for (int t = tid; t < TT; t += 256) {
        float e = g_echunk[b * TT + t];
        if (mask[b * TT + t] == 0) e = NEG_INF;
        se[t] = e;
        mx = fmaxf(mx, e);
    }
    sh[tid] = mx;
    __syncthreads();
    for (int off = 128; off > 0; off >>= 1) {
        if (tid < off) sh[tid] = fmaxf(sh[tid], sh[tid + off]);
        __syncthreads();
    }
    mx = sh[0];
    __syncthreads();

    for (int t = tid; t < TT; t += 256) se[t] = fmaxf(expf(se[t] - mx), 1e-5f);
    __syncthreads();

    // inclusive scan se -> pref (contiguous chunks of 16)
    const int CH = (TT + 255) / 256;  // 16
    int t0 = tid * CH, t1 = min(t0 + CH, TT);
    {
        float s = 0.f;
        for (int t = t0; t < t1; t++) s += se[t];
        sh[tid] = s;
        __syncthreads();
        if (tid == 0) {
            float run = 0.f;
            for (int i = 0; i < 256; i++) { float v = sh[i]; sh[i] = run; run += v; }
        }
        __syncthreads();
        float run = sh[tid];
        for (int t = t0; t < t1; t++) { run += se[t]; pref[t] = run; }
    }
    __syncthreads();

    // q[t] = alpha * TEMP / denom;  denom = pref[t] - pref[t-8]  (window [t-7, t])
    for (int t = tid; t < TT; t += 256) {
        float denom = pref[t] - ((t >= 8) ? pref[t - 8] : 0.f);
        qp[t] = g_alpha[b * TT + t] / denom;   // TEMP = 1
    }
    __syncthreads();

    // inclusive scan qp in place
    {
        float s = 0.f;
        for (int t = t0; t < t1; t++) s += qp[t];
        sh[tid] = s;
        __syncthreads();
        if (tid == 0) {
            float run = 0.f;
            for (int i = 0; i < 256; i++) { float v = sh[i]; sh[i] = run; run += v; }
        }
        __syncthreads();
        float run = sh[tid];
        for (int t = t0; t < t1; t++) { run += qp[t]; qp[t] = run; }
    }
    __syncthreads();

    // beta[t] = se[t] * (qp[min(t+7,T-1)] - qp[t-1])   (window [t, t+7])
    for (int t = tid; t < TT; t += 256) {
        int hi = min(t + 7, TT - 1);
        float ms2 = qp[hi] - ((t > 0) ? qp[t - 1] : 0.f);
        g_beta[b * TT + t] = se[t] * ms2;
    }
}

// ---------------- kernel 4: cv = sum_t beta * value ----------------
__global__ void cv_kernel(const float* __restrict__ value, float* __restrict__ out_cv) {
    int tc = blockIdx.x;   // 32 chunks of 125
    int b  = blockIdx.y;
    int d  = threadIdx.x;  // 512
    float acc = 0.f;
    int t0 = tc * 125;
    for (int t = t0; t < t0 + 125; t++) {
        int row = b * TT + t;
        acc = fmaf(g_beta[row], value[(size_t)row * 512 + d], acc);
    }
    atomicAdd(&out_cv[b * 512 + d], acc);
}

// ---------------- launch ----------------
extern "C" void kernel_launch(void* const* d_in, const int* in_sizes, int n_in,
                              void* d_out, int out_size) {
    const float* key    = (const float*)d_in[0];
    const float* value  = (const float*)d_in[1];
    const float* query  = (const float*)d_in[2];
    const int*   mask   = (const int*)  d_in[3];
    const float* wkm    = (const float*)d_in[4];
    const float* bkm    = (const float*)d_in[5];
    const float* wqm    = (const float*)d_in[6];
    const float* vmono  = (const float*)d_in[7];
    const float* gmono  = (const float*)d_in[8];
    const float* rmono  = (const float*)d_in[9];
    const float* wkc    = (const float*)d_in[10];
    const float* bkc    = (const float*)d_in[11];
    const float* wqc    = (const float*)d_in[12];
    const float* vchunk = (const float*)d_in[13];

    float* out       = (float*)d_out;
    float* out_cv    = out;            // [16, 1, 512] first
    float* out_alpha = out + BB * DD;  // [16, 4000, 1] second

    prep_kernel<<<64, 512>>>(query, wqm, bkm, wqc, bkc, vmono, gmono, out_cv);
    energy_kernel<<<dim3(8, 500), 256>>>(key, wkm, wkc, vchunk);
    mono_scan_kernel<<<16, 128>>>(mask, rmono, out_alpha);
    chunk_post_kernel<<<16, 256>>>(mask);
    cv_kernel<<<dim3(32, 16), 512>>>(value, out_cv);
}

// round 8
// speedup vs baseline: 2.3584x; 2.3584x over previous
#include <cuda_runtime.h>
#include <cstdint>

#define BB 16
#define TT 4000
#define DD 512
#define BT (BB*TT)
#define NEG_INF (-3.4028234663852886e+38f)
#define EPSF 1e-6f

// ---------------- scratch (device globals; no allocation) ----------------
__device__ float g_qb_mono[BB][DD];
__device__ float g_qb_chunk[BB][DD];
__device__ float g_vm[DD];
__device__ float g_emono[BT];
__device__ float g_echunk[BT];
__device__ float g_alpha[BT];
__device__ float g_beta[BT];

// ---------------- JAX threefry2x32 (partitionable path) + XLA erfinv ----------------
__device__ __forceinline__ uint32_t rotl32(uint32_t x, uint32_t r) {
    return (x << r) | (x >> (32u - r));
}

__device__ __forceinline__ float erfinv_xla(float x) {
    float w = -log1pf(-x * x);
    float p;
    if (w < 5.0f) {
        w = w - 2.5f;
        p = 2.81022636e-08f;
        p = fmaf(p, w, 3.43273939e-07f);
        p = fmaf(p, w, -3.5233877e-06f);
        p = fmaf(p, w, -4.39150654e-06f);
        p = fmaf(p, w, 0.00021858087f);
        p = fmaf(p, w, -0.00125372503f);
        p = fmaf(p, w, -0.00417768164f);
        p = fmaf(p, w, 0.246640727f);
        p = fmaf(p, w, 1.50140941f);
    } else {
        w = sqrtf(w) - 3.0f;
        p = -0.000200214257f;
        p = fmaf(p, w, 0.000100950558f);
        p = fmaf(p, w, 0.00134934322f);
        p = fmaf(p, w, -0.00367342844f);
        p = fmaf(p, w, 0.00573950773f);
        p = fmaf(p, w, -0.0076224613f);
        p = fmaf(p, w, 0.00943887047f);
        p = fmaf(p, w, 1.00167406f);
        p = fmaf(p, w, 2.83297682f);
    }
    return p * x;
}

// noise[i] for flattened index i in [0, 64000), key = jax.random.key(123)
// JAX >= 0.4.36 default: jax_threefry_partitionable=True
__device__ float jax_normal_123(int i) {
    const uint32_t k0 = 0u, k1 = 123u;
    const uint32_t k2 = k0 ^ k1 ^ 0x1BD11BDAu;
    uint32_t x0 = k0;                   // counts_hi (=0) + ks[0]
    uint32_t x1 = (uint32_t)i + k1;     // counts_lo (=i) + ks[1]

    #pragma unroll
    for (int r = 0; r < 4; r++) { const uint32_t ra[4] = {13,15,26,6};
        x0 += x1; x1 = rotl32(x1, ra[r]); x1 ^= x0; }
    x0 += k1; x1 += k2 + 1u;
    #pragma unroll
    for (int r = 0; r < 4; r++) { const uint32_t rb[4] = {17,29,16,24};
        x0 += x1; x1 = rotl32(x1, rb[r]); x1 ^= x0; }
    x0 += k2; x1 += k0 + 2u;
    #pragma unroll
    for (int r = 0; r < 4; r++) { const uint32_t ra[4] = {13,15,26,6};
        x0 += x1; x1 = rotl32(x1, ra[r]); x1 ^= x0; }
    x0 += k0; x1 += k1 + 3u;
    #pragma unroll
    for (int r = 0; r < 4; r++) { const uint32_t rb[4] = {17,29,16,24};
        x0 += x1; x1 = rotl32(x1, rb[r]); x1 ^= x0; }
    x0 += k1; x1 += k2 + 4u;
    #pragma unroll
    for (int r = 0; r < 4; r++) { const uint32_t ra[4] = {13,15,26,6};
        x0 += x1; x1 = rotl32(x1, ra[r]); x1 ^= x0; }
    x0 += k2; x1 += k0 + 5u;

    uint32_t bits = x0 ^ x1;            // partitionable 32-bit fold
    float f = __uint_as_float((bits >> 9) | 0x3f800000u) - 1.0f;  // [0,1)
    const float lo = -0.99999994f;                 // nextafter(-1, 0) in f32
    float scale = __fsub_rn(1.0f, lo);             // == 2.0f
    float u = __fadd_rn(__fmul_rn(f, scale), lo);
    u = fmaxf(lo, u);
    return 1.41421356237f * erfinv_xla(u);
}

// ---------------- kernel 0: prep ----------------
__global__ void prep_kernel(const float* __restrict__ query,
                            const float* __restrict__ wqm, const float* __restrict__ bkm,
                            const float* __restrict__ wqc, const float* __restrict__ bkc,
                            const float* __restrict__ vmono, const float* __restrict__ gmono,
                            float* __restrict__ out_cv) {
    int blk = blockIdx.x, tid = threadIdx.x;  // 512 threads
    if (blk < 32) {
        int mat = blk >> 4, b = blk & 15;
        const float* wq   = mat ? wqc : wqm;
        const float* bias = mat ? bkc : bkm;
        const float* q = query + b * DD;
        float s = bias[tid];
        for (int k = 0; k < DD; k++) s = fmaf(q[k], wq[k * DD + tid], s);
        if (mat) g_qb_chunk[b][tid] = s; else g_qb_mono[b][tid] = s;
    } else if (blk == 32) {
        __shared__ float red[512];
        float v = vmono[tid];
        red[tid] = v * v;
        __syncthreads();
        for (int off = 256; off > 0; off >>= 1) {
            if (tid < off) red[tid] += red[tid + off];
            __syncthreads();
        }
        float nrm = sqrtf(red[0]);
        g_vm[tid] = gmono[0] * vmono[tid] / nrm;
    } else {
        int nb = gridDim.x - 33, bi = blk - 33;
        for (int i = bi * 512 + tid; i < 2 * BT; i += nb * 512) {
            if (i < BT) g_emono[i] = 0.f; else g_echunk[i - BT] = 0.f;
        }
        for (int i = bi * 512 + tid; i < BB * DD; i += nb * 512) out_cv[i] = 0.f;
    }
}

// ---------------- kernel 1: fused energy GEMM (tf32 tensor cores) ----------------
__device__ __forceinline__ void mma_tf32(float* c, const uint32_t* a, const uint32_t* b) {
    asm volatile(
        "mma.sync.aligned.m16n8k8.row.col.f32.tf32.tf32.f32 "
        "{%0,%1,%2,%3}, {%4,%5,%6,%7}, {%8,%9}, {%0,%1,%2,%3};\n"
        : "+f"(c[0]), "+f"(c[1]), "+f"(c[2]), "+f"(c[3])
        : "r"(a[0]), "r"(a[1]), "r"(a[2]), "r"(a[3]), "r"(b[0]), "r"(b[1]));
}

__device__ __forceinline__ uint32_t to_tf32(float v) {
    uint32_t t;
    asm("cvt.rna.tf32.f32 %0, %1;" : "=r"(t) : "f"(v));
    return t;
}

// grid (8 colchunks, 500 rowblocks), 256 threads (8 warps: 4 M x 2 N)
// block tile 128M x 128N, warp tile 32M x 64N (m16n8k8 grid 2x8), K-block 32
__global__ __launch_bounds__(256, 2) void energy_kernel(
    const float* __restrict__ key, const float* __restrict__ wm,
    const float* __restrict__ wc,  const float* __restrict__ vchunk) {
    __shared__ float As[128][36];   // [m][k], pad -> (4g+q)%32 distinct: conflict-free frags
    __shared__ float Bs[32][136];   // [k][n], pad -> (8q+g)%32 distinct: conflict-free frags
    int tid  = threadIdx.x;
    int lane = tid & 31, wid = tid >> 5;
    int g = lane >> 2, q = lane & 3;
    int warp_m = wid & 3, warp_n = wid >> 2;
    int row0 = blockIdx.y * 128;
    int cc = blockIdx.x;
    int mat = cc >> 2;
    int a0 = (cc & 3) * 128;
    const float* W = mat ? wc : wm;

    float acc[2][8][4];
    #pragma unroll
    for (int mi = 0; mi < 2; mi++)
        #pragma unroll
        for (int ni = 0; ni < 8; ni++)
            #pragma unroll
            for (int x = 0; x < 4; x++) acc[mi][ni][x] = 0.f;

    for (int kb = 0; kb < 16; kb++) {
        int kbase = kb * 32;
        __syncthreads();
        #pragma unroll
        for (int p = 0; p < 16; p++) {
            int idx = tid + p * 256;
            int kk = idx & 31, m = idx >> 5;
            float v = fmaxf(key[(size_t)(row0 + m) * 512 + kbase + kk], 0.f);  // relu
            As[m][kk] = __uint_as_float(to_tf32(v));
        }
        #pragma unroll
        for (int p = 0; p < 16; p++) {
            int idx = tid + p * 256;
            int n = idx & 127, kk = idx >> 7;
            float v = W[(size_t)(kbase + kk) * 512 + a0 + n];
            Bs[kk][n] = __uint_as_float(to_tf32(v));
        }
        __syncthreads();
        #pragma unroll
        for (int ks = 0; ks < 4; ks++) {
            int kk = ks * 8;
            uint32_t afr[2][4];
            #pragma unroll
            for (int mi = 0; mi < 2; mi++) {
                int r = warp_m * 32 + mi * 16;
                afr[mi][0] = __float_as_uint(As[r + g    ][kk + q    ]);
                afr[mi][1] = __float_as_uint(As[r + g + 8][kk + q    ]);
                afr[mi][2] = __float_as_uint(As[r + g    ][kk + q + 4]);
                afr[mi][3] = __float_as_uint(As[r + g + 8][kk + q + 4]);
            }
            #pragma unroll
            for (int ni = 0; ni < 8; ni++) {
                uint32_t bfr[2];
                int n = warp_n * 64 + ni * 8 + g;
                bfr[0] = __float_as_uint(Bs[kk + q    ][n]);
                bfr[1] = __float_as_uint(Bs[kk + q + 4][n]);
                mma_tf32(acc[0][ni], afr[0], bfr);
                mma_tf32(acc[1][ni], afr[1], bfr);
            }
        }
    }
    __syncthreads();

    // epilogue: e_partial(row) = sum_a tanh(acc + qb[b][a]) * v[a]
    const float* qbp = mat ? &g_qb_chunk[0][0] : &g_qb_mono[0][0];
    const float* vp  = mat ? vchunk : g_vm;
    float* eout      = mat ? g_echunk : g_emono;
    float (*red)[9]  = (float(*)[9])&As[0][0];  // 128 x 9, overlays As

    #pragma unroll
    for (int mi = 0; mi < 2; mi++) {
        #pragma unroll
        for (int half = 0; half < 2; half++) {
            int lr = warp_m * 32 + mi * 16 + half * 8 + g;
            int b  = (row0 + lr) / TT;
            const float* qb = qbp + b * DD + a0;
            float s = 0.f;
            #pragma unroll
            for (int ni = 0; ni < 8; ni++) {
                int n = warp_n * 64 + ni * 8 + 2 * q;
                float c0 = acc[mi][ni][half * 2 + 0];
                float c1 = acc[mi][ni][half * 2 + 1];
                s = fmaf(tanhf(c0 + qb[n]),     vp[a0 + n],     s);
                s = fmaf(tanhf(c1 + qb[n + 1]), vp[a0 + n + 1], s);
            }
            red[lr][warp_n * 4 + q] = s;
        }
    }
    __syncthreads();
    if (tid < 128) {
        float s = 0.f;
        #pragma unroll
        for (int x = 0; x < 8; x++) s += red[tid][x];
        atomicAdd(&eout[row0 + tid], s);
    }
}

// ---------------- kernel 2: noise + p + alpha scan ----------------
__global__ void mono_scan_kernel(const int* __restrict__ mask,
                                 const float* __restrict__ rmono,
                                 float* __restrict__ out_alpha) {
    int b = blockIdx.x, tid = threadIdx.x;  // 128 threads
    __shared__ float lp[TT];
    __shared__ float pp[TT];
    __shared__ float partial[129];
    float r = rmono[0];
    const int CH = (TT + 127) / 128;  // 32
    int t0 = tid * CH, t1 = min(t0 + CH, TT);
    float s = 0.f;
    for (int t = t0; t < t1; t++) {
        int i = b * TT + t;
        float e = g_emono[i] + r;
        if (mask[i] == 0) e = NEG_INF;
        float x = e + jax_normal_123(i);
        float p = 1.f / (1.f + expf(-x));
        float l = logf(fminf(fmaxf(1.f - p, EPSF), 1.f));
        pp[t] = p; lp[t] = l; s += l;
    }
    partial[tid] = s;
    __syncthreads();
    if (tid == 0) {
        float run = 0.f;
        for (int i = 0; i < 128; i++) { float v = partial[i]; partial[i] = run; run += v; }
    }
    __syncthreads();
    float run = partial[tid];
    for (int t = t0; t < t1; t++) {
        float al = pp[t] * expf(run);   // exclusive cumsum -> cumprod
        run += lp[t];
        g_alpha[b * TT + t] = al;
        out_alpha[b * TT + t] = al;
    }
}

// ---------------- kernel 3: chunk energies -> beta ----------------
__global__ void chunk_post_kernel(const int* __restrict__ mask) {
    int b = blockIdx.x, tid = threadIdx.x;  // 256 threads
    __shared__ float se[TT];
    __shared__ float pref[TT];
    __shared__ float qp[TT];
    __shared__ float sh[257];

    float mx = -3.4e38f;
    for (int t = tid; t < TT; t += 256) {
        float e = g_echunk[b * TT + t];
        if (mask[b * TT + t] == 0) e = NEG_INF;
        se[t] = e;
        mx = fmaxf(mx, e);
    }
    sh[tid] = mx;
    __syncthreads();
    for (int off = 128; off > 0; off >>= 1) {
        if (tid < off) sh[tid] = fmaxf(sh[tid], sh[tid + off]);
        __syncthreads();
    }
    mx = sh[0];
    __syncthreads();

    for (int t = tid; t < TT; t += 256) se[t] = fmaxf(expf(se[t] - mx), 1e-5f);
    __syncthreads();

    const int CH = (TT + 255) / 256;  // 16
    int t0 = tid * CH, t1 = min(t0 + CH, TT);
    {
        float s = 0.f;
        for (int t = t0; t < t1; t++) s += se[t];
        sh[tid] = s;
        __syncthreads();
        if (tid == 0) {
            float run = 0.f;
            for (int i = 0; i < 256; i++) { float v = sh[i]; sh[i] = run; run += v; }
        }
        __syncthreads();
        float run = sh[tid];
        for (int t = t0; t < t1; t++) { run += se[t]; pref[t] = run; }
    }
    __syncthreads();

    for (int t = tid; t < TT; t += 256) {
        float denom = pref[t] - ((t >= 8) ? pref[t - 8] : 0.f);
        qp[t] = g_alpha[b * TT + t] / denom;   // TEMP = 1
    }
    __syncthreads();

    {
        float s = 0.f;
        for (int t = t0; t < t1; t++) s += qp[t];
        sh[tid] = s;
        __syncthreads();
        if (tid == 0) {
            float run = 0.f;
            for (int i = 0; i < 256; i++) { float v = sh[i]; sh[i] = run; run += v; }
        }
        __syncthreads();
        float run = sh[tid];
        for (int t = t0; t < t1; t++) { run += qp[t]; qp[t] = run; }
    }
    __syncthreads();

    for (int t = tid; t < TT; t += 256) {
        int hi = min(t + 7, TT - 1);
        float ms2 = qp[hi] - ((t > 0) ? qp[t - 1] : 0.f);
        g_beta[b * TT + t] = se[t] * ms2;
    }
}

// ---------------- kernel 4: cv = sum_t beta * value ----------------
__global__ void cv_kernel(const float* __restrict__ value, float* __restrict__ out_cv) {
    int tc = blockIdx.x;   // 32 chunks of 125
    int b  = blockIdx.y;
    int d  = threadIdx.x;  // 512
    float acc = 0.f;
    int t0 = tc * 125;
    for (int t = t0; t < t0 + 125; t++) {
        int row = b * TT + t;
        acc = fmaf(g_beta[row], value[(size_t)row * 512 + d], acc);
    }
    atomicAdd(&out_cv[b * 512 + d], acc);
}

// ---------------- launch ----------------
extern "C" void kernel_launch(void* const* d_in, const int* in_sizes, int n_in,
                              void* d_out, int out_size) {
    const float* key    = (const float*)d_in[0];
    const float* value  = (const float*)d_in[1];
    const float* query  = (const float*)d_in[2];
    const int*   mask   = (const int*)  d_in[3];
    const float* wkm    = (const float*)d_in[4];
    const float* bkm    = (const float*)d_in[5];
    const float* wqm    = (const float*)d_in[6];
    const float* vmono  = (const float*)d_in[7];
    const float* gmono  = (const float*)d_in[8];
    const float* rmono  = (const float*)d_in[9];
    const float* wkc    = (const float*)d_in[10];
    const float* bkc    = (const float*)d_in[11];
    const float* wqc    = (const float*)d_in[12];
    const float* vchunk = (const float*)d_in[13];

    float* out       = (float*)d_out;
    float* out_cv    = out;            // [16, 1, 512] first
    float* out_alpha = out + BB * DD;  // [16, 4000, 1] second

    prep_kernel<<<64, 512>>>(query, wqm, bkm, wqc, bkc, vmono, gmono, out_cv);
    energy_kernel<<<dim3(8, 500), 256>>>(key, wkm, wkc, vchunk);
    mono_scan_kernel<<<16, 128>>>(mask, rmono, out_alpha);
    chunk_post_kernel<<<16, 256>>>(mask);
    cv_kernel<<<dim3(32, 16), 512>>>(value, out_cv);
}

// round 10
// speedup vs baseline: 2.7538x; 1.1677x over previous
#include <cuda_runtime.h>
#include <cstdint>

#define BB 16
#define TT 4000
#define DD 512
#define BT (BB*TT)
#define NEG_INF (-3.4028234663852886e+38f)
#define EPSF 1e-6f

// ---------------- scratch (device globals; no allocation) ----------------
__device__ float g_qb_mono[BB][DD];
__device__ float g_qb_chunk[BB][DD];
__device__ float g_vm[DD];
__device__ float g_emono[BT];
__device__ float g_echunk[BT];
__device__ float g_alpha[BT];
__device__ float g_beta[BT];

// ---------------- JAX threefry2x32 (partitionable path) + XLA erfinv ----------------
__device__ __forceinline__ uint32_t rotl32(uint32_t x, uint32_t r) {
    return (x << r) | (x >> (32u - r));
}

__device__ __forceinline__ float erfinv_xla(float x) {
    float w = -log1pf(-x * x);
    float p;
    if (w < 5.0f) {
        w = w - 2.5f;
        p = 2.81022636e-08f;
        p = fmaf(p, w, 3.43273939e-07f);
        p = fmaf(p, w, -3.5233877e-06f);
        p = fmaf(p, w, -4.39150654e-06f);
        p = fmaf(p, w, 0.00021858087f);
        p = fmaf(p, w, -0.00125372503f);
        p = fmaf(p, w, -0.00417768164f);
        p = fmaf(p, w, 0.246640727f);
        p = fmaf(p, w, 1.50140941f);
    } else {
        w = sqrtf(w) - 3.0f;
        p = -0.000200214257f;
        p = fmaf(p, w, 0.000100950558f);
        p = fmaf(p, w, 0.00134934322f);
        p = fmaf(p, w, -0.00367342844f);
        p = fmaf(p, w, 0.00573950773f);
        p = fmaf(p, w, -0.0076224613f);
        p = fmaf(p, w, 0.00943887047f);
        p = fmaf(p, w, 1.00167406f);
        p = fmaf(p, w, 2.83297682f);
    }
    return p * x;
}

// noise[i] for flattened index i in [0, 64000), key = jax.random.key(123)
// JAX >= 0.4.36 default: jax_threefry_partitionable=True
__device__ float jax_normal_123(int i) {
    const uint32_t k0 = 0u, k1 = 123u;
    const uint32_t k2 = k0 ^ k1 ^ 0x1BD11BDAu;
    uint32_t x0 = k0;                   // counts_hi (=0) + ks[0]
    uint32_t x1 = (uint32_t)i + k1;     // counts_lo (=i) + ks[1]

    #pragma unroll
    for (int r = 0; r < 4; r++) { const uint32_t ra[4] = {13,15,26,6};
        x0 += x1; x1 = rotl32(x1, ra[r]); x1 ^= x0; }
    x0 += k1; x1 += k2 + 1u;
    #pragma unroll
    for (int r = 0; r < 4; r++) { const uint32_t rb[4] = {17,29,16,24};
        x0 += x1; x1 = rotl32(x1, rb[r]); x1 ^= x0; }
    x0 += k2; x1 += k0 + 2u;
    #pragma unroll
    for (int r = 0; r < 4; r++) { const uint32_t ra[4] = {13,15,26,6};
        x0 += x1; x1 = rotl32(x1, ra[r]); x1 ^= x0; }
    x0 += k0; x1 += k1 + 3u;
    #pragma unroll
    for (int r = 0; r < 4; r++) { const uint32_t rb[4] = {17,29,16,24};
        x0 += x1; x1 = rotl32(x1, rb[r]); x1 ^= x0; }
    x0 += k1; x1 += k2 + 4u;
    #pragma unroll
    for (int r = 0; r < 4; r++) { const uint32_t ra[4] = {13,15,26,6};
        x0 += x1; x1 = rotl32(x1, ra[r]); x1 ^= x0; }
    x0 += k2; x1 += k0 + 5u;

    uint32_t bits = x0 ^ x1;            // partitionable 32-bit fold
    float f = __uint_as_float((bits >> 9) | 0x3f800000u) - 1.0f;  // [0,1)
    const float lo = -0.99999994f;                 // nextafter(-1, 0) in f32
    float scale = __fsub_rn(1.0f, lo);             // == 2.0f
    float u = __fadd_rn(__fmul_rn(f, scale), lo);
    u = fmaxf(lo, u);
    return 1.41421356237f * erfinv_xla(u);
}

// ---------------- kernel 0: prep ----------------
__global__ void prep_kernel(const float* __restrict__ query,
                            const float* __restrict__ wqm, const float* __restrict__ bkm,
                            const float* __restrict__ wqc, const float* __restrict__ bkc,
                            const float* __restrict__ vmono, const float* __restrict__ gmono,
                            float* __restrict__ out_cv) {
    int blk = blockIdx.x, tid = threadIdx.x;  // 512 threads
    if (blk < 32) {
        int mat = blk >> 4, b = blk & 15;
        const float* wq   = mat ? wqc : wqm;
        const float* bias = mat ? bkc : bkm;
        const float* q = query + b * DD;
        float s = bias[tid];
        for (int k = 0; k < DD; k++) s = fmaf(q[k], wq[k * DD + tid], s);
        if (mat) g_qb_chunk[b][tid] = s; else g_qb_mono[b][tid] = s;
    } else if (blk == 32) {
        __shared__ float red[512];
        float v = vmono[tid];
        red[tid] = v * v;
        __syncthreads();
        for (int off = 256; off > 0; off >>= 1) {
            if (tid < off) red[tid] += red[tid + off];
            __syncthreads();
        }
        float nrm = sqrtf(red[0]);
        g_vm[tid] = gmono[0] * vmono[tid] / nrm;
    } else {
        int nb = gridDim.x - 33, bi = blk - 33;
        for (int i = bi * 512 + tid; i < 2 * BT; i += nb * 512) {
            if (i < BT) g_emono[i] = 0.f; else g_echunk[i - BT] = 0.f;
        }
        for (int i = bi * 512 + tid; i < BB * DD; i += nb * 512) out_cv[i] = 0.f;
    }
}

// ---------------- kernel 1: fused energy GEMM (tf32 MMA + cp.async pipeline) ----------------
__device__ __forceinline__ void mma_tf32(float* c, const uint32_t* a, const uint32_t* b) {
    asm volatile(
        "mma.sync.aligned.m16n8k8.row.col.f32.tf32.tf32.f32 "
        "{%0,%1,%2,%3}, {%4,%5,%6,%7}, {%8,%9}, {%0,%1,%2,%3};\n"
        : "+f"(c[0]), "+f"(c[1]), "+f"(c[2]), "+f"(c[3])
        : "r"(a[0]), "r"(a[1]), "r"(a[2]), "r"(a[3]), "r"(b[0]), "r"(b[1]));
}

__device__ __forceinline__ uint32_t to_tf32(float v) {
    uint32_t t;
    asm("cvt.rna.tf32.f32 %0, %1;" : "=r"(t) : "f"(v));
    return t;
}

__device__ __forceinline__ void cp16(uint32_t dst, const void* src) {
    asm volatile("cp.async.cg.shared.global [%0], [%1], 16;" :: "r"(dst), "l"(src));
}

#define AS_STRIDE 36
#define BS_STRIDE 136
#define AS_BUF (128 * AS_STRIDE)
#define BS_BUF (32 * BS_STRIDE)
#define SMEM_FLOATS (2 * AS_BUF + 2 * BS_BUF)   // 17920 floats = 71680 B

// grid (8 colchunks, 500 rowblocks), 256 threads (8 warps: 4 M x 2 N)
// block tile 128M x 128N, warp tile 32M x 64N (m16n8k8 grid 2x8), K-block 32, 2-stage cp.async
__global__ __launch_bounds__(256, 2) void energy_kernel(
    const float* __restrict__ key, const float* __restrict__ wm,
    const float* __restrict__ wc,  const float* __restrict__ vchunk) {
    extern __shared__ float smem[];
    float* As = smem;                 // [2][128][36]
    float* Bs = smem + 2 * AS_BUF;    // [2][32][136]

    int tid  = threadIdx.x;
    int lane = tid & 31, wid = tid >> 5;
    int g = lane >> 2, q = lane & 3;
    int warp_m = wid & 3, warp_n = wid >> 2;
    int row0 = blockIdx.y * 128;
    int cc = blockIdx.x;
    int mat = cc >> 2;
    int a0 = (cc & 3) * 128;
    const float* W = mat ? wc : wm;

    // per-thread cp.async source/dest precompute
    int am = tid >> 3, ac4 = tid & 7;     // A: 4 rows-chunks per phase below
    int bk = tid >> 5, bc4 = tid & 31;    // B
    uint32_t as_base = (uint32_t)__cvta_generic_to_shared(As);
    uint32_t bs_base = (uint32_t)__cvta_generic_to_shared(Bs);

    float acc[2][8][4];
    #pragma unroll
    for (int mi = 0; mi < 2; mi++)
        #pragma unroll
        for (int ni = 0; ni < 8; ni++)
            #pragma unroll
            for (int x = 0; x < 4; x++) acc[mi][ni][x] = 0.f;

    // prefetch helper (stage kb into buffer buf)
    #define PREFETCH(kb, buf) do {                                              \
        int kbase = (kb) * 32;                                                  \
        _Pragma("unroll")                                                       \
        for (int p = 0; p < 4; p++) {                                           \
            int m = am + p * 32;                                                \
            cp16(as_base + ((buf) * AS_BUF + m * AS_STRIDE + ac4 * 4) * 4,      \
                 key + (size_t)(row0 + m) * 512 + kbase + ac4 * 4);             \
        }                                                                       \
        _Pragma("unroll")                                                       \
        for (int p = 0; p < 4; p++) {                                           \
            int kk = bk + p * 8;                                                \
            cp16(bs_base + ((buf) * BS_BUF + kk * BS_STRIDE + bc4 * 4) * 4,     \
                 W + (size_t)(kbase + kk) * 512 + a0 + bc4 * 4);                \
        }                                                                       \
        asm volatile("cp.async.commit_group;");                                 \
    } while (0)

    PREFETCH(0, 0);

    for (int kb = 0; kb < 16; kb++) {
        int buf = kb & 1;
        if (kb + 1 < 16) {
            PREFETCH(kb + 1, buf ^ 1);
            asm volatile("cp.async.wait_group 1;");
        } else {
            asm volatile("cp.async.wait_group 0;");
        }
        __syncthreads();

        const float* Ab = As + buf * AS_BUF;
        const float* Bb = Bs + buf * BS_BUF;
        #pragma unroll
        for (int ks = 0; ks < 4; ks++) {
            int kk = ks * 8;
            uint32_t afr[2][4];
            #pragma unroll
            for (int mi = 0; mi < 2; mi++) {
                int r = warp_m * 32 + mi * 16;
                afr[mi][0] = to_tf32(fmaxf(Ab[(r + g    ) * AS_STRIDE + kk + q    ], 0.f));
                afr[mi][1] = to_tf32(fmaxf(Ab[(r + g + 8) * AS_STRIDE + kk + q    ], 0.f));
                afr[mi][2] = to_tf32(fmaxf(Ab[(r + g    ) * AS_STRIDE + kk + q + 4], 0.f));
                afr[mi][3] = to_tf32(fmaxf(Ab[(r + g + 8) * AS_STRIDE + kk + q + 4], 0.f));
            }
            #pragma unroll
            for (int ni = 0; ni < 8; ni++) {
                uint32_t bfr[2];
                int n = warp_n * 64 + ni * 8 + g;
                bfr[0] = to_tf32(Bb[(kk + q    ) * BS_STRIDE + n]);
                bfr[1] = to_tf32(Bb[(kk + q + 4) * BS_STRIDE + n]);
                mma_tf32(acc[0][ni], afr[0], bfr);
                mma_tf32(acc[1][ni], afr[1], bfr);
            }
        }
        __syncthreads();
    }

    // epilogue: e_partial(row) = sum_a tanh(acc + qb[b][a]) * v[a]
    const float* qbp = mat ? &g_qb_chunk[0][0] : &g_qb_mono[0][0];
    const float* vp  = mat ? vchunk : g_vm;
    float* eout      = mat ? g_echunk : g_emono;
    float (*red)[9]  = (float(*)[9])smem;  // 128 x 9, overlays As

    #pragma unroll
    for (int mi = 0; mi < 2; mi++) {
        #pragma unroll
        for (int half = 0; half < 2; half++) {
            int lr = warp_m * 32 + mi * 16 + half * 8 + g;
            int b  = (row0 + lr) / TT;
            const float* qb = qbp + b * DD + a0;
            float s = 0.f;
            #pragma unroll
            for (int ni = 0; ni < 8; ni++) {
                int n = warp_n * 64 + ni * 8 + 2 * q;
                float c0 = acc[mi][ni][half * 2 + 0];
                float c1 = acc[mi][ni][half * 2 + 1];
                s = fmaf(tanhf(c0 + qb[n]),     vp[a0 + n],     s);
                s = fmaf(tanhf(c1 + qb[n + 1]), vp[a0 + n + 1], s);
            }
            red[lr][warp_n * 4 + q] = s;
        }
    }
    __syncthreads();
    if (tid < 128) {
        float s = 0.f;
        #pragma unroll
        for (int x = 0; x < 8; x++) s += red[tid][x];
        atomicAdd(&eout[row0 + tid], s);
    }
    #undef PREFETCH
}

// ---------------- kernel 2: noise + p + alpha scan ----------------
__global__ void mono_scan_kernel(const int* __restrict__ mask,
                                 const float* __restrict__ rmono,
                                 float* __restrict__ out_alpha) {
    int b = blockIdx.x, tid = threadIdx.x;  // 128 threads
    __shared__ float lp[TT];
    __shared__ float pp[TT];
    __shared__ float partial[129];
    float r = rmono[0];
    const int CH = (TT + 127) / 128;  // 32
    int t0 = tid * CH, t1 = min(t0 + CH, TT);
    float s = 0.f;
    for (int t = t0; t < t1; t++) {
        int i = b * TT + t;
        float e = g_emono[i] + r;
        if (mask[i] == 0) e = NEG_INF;
        float x = e + jax_normal_123(i);
        float p = 1.f / (1.f + expf(-x));
        float l = logf(fminf(fmaxf(1.f - p, EPSF), 1.f));
        pp[t] = p; lp[t] = l; s += l;
    }
    partial[tid] = s;
    __syncthreads();
    if (tid == 0) {
        float run = 0.f;
        for (int i = 0; i < 128; i++) { float v = partial[i]; partial[i] = run; run += v; }
    }
    __syncthreads();
    float run = partial[tid];
    for (int t = t0; t < t1; t++) {
        float al = pp[t] * expf(run);   // exclusive cumsum -> cumprod
        run += lp[t];
        g_alpha[b * TT + t] = al;
        out_alpha[b * TT + t] = al;
    }
}

// ---------------- kernel 3: chunk energies -> beta ----------------
__global__ void chunk_post_kernel(const int* __restrict__ mask) {
    int b = blockIdx.x, tid = threadIdx.x;  // 256 threads
    __shared__ float se[TT];
    __shared__ float pref[TT];
    __shared__ float qp[TT];
    __shared__ float sh[257];

    float mx = -3.4e38f;
    for (int t = tid; t < TT; t += 256) {
        float e = g_echunk[b * TT + t];
        if (mask[b * TT + t] == 0) e = NEG_INF;
        se[t] = e;
        mx = fmaxf(mx, e);
    }
    sh[tid] = mx;
    __syncthreads();
    for (int off = 128; off > 0; off >>= 1) {
        if (tid < off) sh[tid] = fmaxf(sh[tid], sh[tid + off]);
        __syncthreads();
    }
    mx = sh[0];
    __syncthreads();

    for (int t = tid; t < TT; t += 256) se[t] = fmaxf(expf(se[t] - mx), 1e-5f);
    __syncthreads();

    const int CH = (TT + 255) / 256;  // 16
    int t0 = tid * CH, t1 = min(t0 + CH, TT);
    {
        float s = 0.f;
        for (int t = t0; t < t1; t++) s += se[t];
        sh[tid] = s;
        __syncthreads();
        if (tid == 0) {
            float run = 0.f;
            for (int i = 0; i < 256; i++) { float v = sh[i]; sh[i] = run; run += v; }
        }
        __syncthreads();
        float run = sh[tid];
        for (int t = t0; t < t1; t++) { run += se[t]; pref[t] = run; }
    }
    __syncthreads();

    for (int t = tid; t < TT; t += 256) {
        float denom = pref[t] - ((t >= 8) ? pref[t - 8] : 0.f);
        qp[t] = g_alpha[b * TT + t] / denom;   // TEMP = 1
    }
    __syncthreads();

    {
        float s = 0.f;
        for (int t = t0; t < t1; t++) s += qp[t];
        sh[tid] = s;
        __syncthreads();
        if (tid == 0) {
            float run = 0.f;
            for (int i = 0; i < 256; i++) { float v = sh[i]; sh[i] = run; run += v; }
        }
        __syncthreads();
        float run = sh[tid];
        for (int t = t0; t < t1; t++) { run += qp[t]; qp[t] = run; }
    }
    __syncthreads();

    for (int t = tid; t < TT; t += 256) {
        int hi = min(t + 7, TT - 1);
        float ms2 = qp[hi] - ((t > 0) ? qp[t - 1] : 0.f);
        g_beta[b * TT + t] = se[t] * ms2;
    }
}

// ---------------- kernel 4: cv = sum_t beta * value ----------------
__global__ void cv_kernel(const float* __restrict__ value, float* __restrict__ out_cv) {
    int tc = blockIdx.x;   // 32 chunks of 125
    int b  = blockIdx.y;
    int d  = threadIdx.x;  // 512
    float acc = 0.f;
    int t0 = tc * 125;
    for (int t = t0; t < t0 + 125; t++) {
        int row = b * TT + t;
        acc = fmaf(g_beta[row], value[(size_t)row * 512 + d], acc);
    }
    atomicAdd(&out_cv[b * 512 + d], acc);
}

// ---------------- launch ----------------
extern "C" void kernel_launch(void* const* d_in, const int* in_sizes, int n_in,
                              void* d_out, int out_size) {
    const float* key    = (const float*)d_in[0];
    const float* value  = (const float*)d_in[1];
    const float* query  = (const float*)d_in[2];
    const int*   mask   = (const int*)  d_in[3];
    const float* wkm    = (const float*)d_in[4];
    const float* bkm    = (const float*)d_in[5];
    const float* wqm    = (const float*)d_in[6];
    const float* vmono  = (const float*)d_in[7];
    const float* gmono  = (const float*)d_in[8];
    const float* rmono  = (const float*)d_in[9];
    const float* wkc    = (const float*)d_in[10];
    const float* bkc    = (const float*)d_in[11];
    const float* wqc    = (const float*)d_in[12];
    const float* vchunk = (const float*)d_in[13];

    float* out       = (float*)d_out;
    float* out_cv    = out;            // [16, 1, 512] first
    float* out_alpha = out + BB * DD;  // [16, 4000, 1] second

    const int smem_bytes = SMEM_FLOATS * 4;  // 71680
    cudaFuncSetAttribute(energy_kernel, cudaFuncAttributeMaxDynamicSharedMemorySize, smem_bytes);

    prep_kernel<<<64, 512>>>(query, wqm, bkm, wqc, bkc, vmono, gmono, out_cv);
    energy_kernel<<<dim3(8, 500), 256, smem_bytes>>>(key, wkm, wkc, vchunk);
    mono_scan_kernel<<<16, 128>>>(mask, rmono, out_alpha);
    chunk_post_kernel<<<16, 256>>>(mask);
    cv_kernel<<<dim3(32, 16), 512>>>(value, out_cv);
}

// round 11
// speedup vs baseline: 3.4644x; 1.2580x over previous
#include <cuda_runtime.h>
#include <cstdint>

#define BB 16
#define TT 4000
#define DD 512
#define BT (BB*TT)
#define NEG_INF (-3.4028234663852886e+38f)
#define EPSF 1e-6f

// ---------------- scratch (device globals; no allocation) ----------------
__device__ float g_qb_mono[BB][DD];
__device__ float g_qb_chunk[BB][DD];
__device__ float g_vm[DD];
__device__ float g_emono[BT];
__device__ float g_echunk[BT];
__device__ float g_alpha[BT];
__device__ float g_beta[BT];
__device__ float g_wt[2][DD * DD];   // transposed + tf32-rounded weights, [mat][n][k]

// ---------------- JAX threefry2x32 (partitionable path) + XLA erfinv ----------------
__device__ __forceinline__ uint32_t rotl32(uint32_t x, uint32_t r) {
    return (x << r) | (x >> (32u - r));
}

__device__ __forceinline__ float erfinv_xla(float x) {
    float w = -log1pf(-x * x);
    float p;
    if (w < 5.0f) {
        w = w - 2.5f;
        p = 2.81022636e-08f;
        p = fmaf(p, w, 3.43273939e-07f);
        p = fmaf(p, w, -3.5233877e-06f);
        p = fmaf(p, w, -4.39150654e-06f);
        p = fmaf(p, w, 0.00021858087f);
        p = fmaf(p, w, -0.00125372503f);
        p = fmaf(p, w, -0.00417768164f);
        p = fmaf(p, w, 0.246640727f);
        p = fmaf(p, w, 1.50140941f);
    } else {
        w = sqrtf(w) - 3.0f;
        p = -0.000200214257f;
        p = fmaf(p, w, 0.000100950558f);
        p = fmaf(p, w, 0.00134934322f);
        p = fmaf(p, w, -0.00367342844f);
        p = fmaf(p, w, 0.00573950773f);
        p = fmaf(p, w, -0.0076224613f);
        p = fmaf(p, w, 0.00943887047f);
        p = fmaf(p, w, 1.00167406f);
        p = fmaf(p, w, 2.83297682f);
    }
    return p * x;
}

// noise[i] for flattened index i in [0, 64000), key = jax.random.key(123)
// JAX >= 0.4.36 default: jax_threefry_partitionable=True
__device__ float jax_normal_123(int i) {
    const uint32_t k0 = 0u, k1 = 123u;
    const uint32_t k2 = k0 ^ k1 ^ 0x1BD11BDAu;
    uint32_t x0 = k0;
    uint32_t x1 = (uint32_t)i + k1;

    #pragma unroll
    for (int r = 0; r < 4; r++) { const uint32_t ra[4] = {13,15,26,6};
        x0 += x1; x1 = rotl32(x1, ra[r]); x1 ^= x0; }
    x0 += k1; x1 += k2 + 1u;
    #pragma unroll
    for (int r = 0; r < 4; r++) { const uint32_t rb[4] = {17,29,16,24};
        x0 += x1; x1 = rotl32(x1, rb[r]); x1 ^= x0; }
    x0 += k2; x1 += k0 + 2u;
    #pragma unroll
    for (int r = 0; r < 4; r++) { const uint32_t ra[4] = {13,15,26,6};
        x0 += x1; x1 = rotl32(x1, ra[r]); x1 ^= x0; }
    x0 += k0; x1 += k1 + 3u;
    #pragma unroll
    for (int r = 0; r < 4; r++) { const uint32_t rb[4] = {17,29,16,24};
        x0 += x1; x1 = rotl32(x1, rb[r]); x1 ^= x0; }
    x0 += k1; x1 += k2 + 4u;
    #pragma unroll
    for (int r = 0; r < 4; r++) { const uint32_t ra[4] = {13,15,26,6};
        x0 += x1; x1 = rotl32(x1, ra[r]); x1 ^= x0; }
    x0 += k2; x1 += k0 + 5u;

    uint32_t bits = x0 ^ x1;
    float f = __uint_as_float((bits >> 9) | 0x3f800000u) - 1.0f;  // [0,1)
    const float lo = -0.99999994f;
    float scale = __fsub_rn(1.0f, lo);             // == 2.0f
    float u = __fadd_rn(__fmul_rn(f, scale), lo);
    u = fmaxf(lo, u);
    return 1.41421356237f * erfinv_xla(u);
}

// ---------------- shfl-based block exclusive scan ----------------
__device__ __forceinline__ float block_excl_scan(float v, int tid, int nthreads, float* ws) {
    __syncthreads();                    // protect ws reuse
    int lane = tid & 31, w = tid >> 5, nw = nthreads >> 5;
    float x = v;
    #pragma unroll
    for (int o = 1; o < 32; o <<= 1) {
        float y = __shfl_up_sync(0xffffffffu, x, o);
        if (lane >= o) x += y;
    }
    if (lane == 31) ws[w] = x;
    __syncthreads();
    if (w == 0) {
        float s = (lane < nw) ? ws[lane] : 0.f;
        float xs = s;
        #pragma unroll
        for (int o = 1; o < 32; o <<= 1) {
            float y = __shfl_up_sync(0xffffffffu, xs, o);
            if (lane >= o) xs += y;
        }
        if (lane < nw) ws[lane] = xs - s;   // exclusive warp sums
    }
    __syncthreads();
    return ws[w] + (x - v);                 // block-exclusive prefix for this thread
}

// ---------------- kernel 0: prep ----------------
__global__ void prep_kernel(const float* __restrict__ query,
                            const float* __restrict__ wqm, const float* __restrict__ bkm,
                            const float* __restrict__ wqc, const float* __restrict__ bkc,
                            const float* __restrict__ vmono, const float* __restrict__ gmono,
                            float* __restrict__ out_cv) {
    int blk = blockIdx.x, tid = threadIdx.x;  // 512 threads
    if (blk < 32) {
        int mat = blk >> 4, b = blk & 15;
        const float* wq   = mat ? wqc : wqm;
        const float* bias = mat ? bkc : bkm;
        const float* q = query + b * DD;
        float s = bias[tid];
        for (int k = 0; k < DD; k++) s = fmaf(q[k], wq[k * DD + tid], s);
        if (mat) g_qb_chunk[b][tid] = s; else g_qb_mono[b][tid] = s;
    } else if (blk == 32) {
        __shared__ float red[512];
        float v = vmono[tid];
        red[tid] = v * v;
        __syncthreads();
        for (int off = 256; off > 0; off >>= 1) {
            if (tid < off) red[tid] += red[tid + off];
            __syncthreads();
        }
        float nrm = sqrtf(red[0]);
        g_vm[tid] = gmono[0] * vmono[tid] / nrm;
    } else {
        int nb = gridDim.x - 33, bi = blk - 33;
        for (int i = bi * 512 + tid; i < 2 * BT; i += nb * 512) {
            if (i < BT) g_emono[i] = 0.f; else g_echunk[i - BT] = 0.f;
        }
        for (int i = bi * 512 + tid; i < BB * DD; i += nb * 512) out_cv[i] = 0.f;
    }
}

// ---------------- kernel 0b: weight transpose + tf32 pre-round ----------------
__device__ __forceinline__ uint32_t to_tf32(float v) {
    uint32_t t;
    asm("cvt.rna.tf32.f32 %0, %1;" : "=r"(t) : "f"(v));
    return t;
}

__global__ void wt_kernel(const float* __restrict__ wm, const float* __restrict__ wc) {
    __shared__ float tile[32][33];
    const float* W = blockIdx.z ? wc : wm;
    int k0 = blockIdx.x * 32, n0 = blockIdx.y * 32;
    for (int r = threadIdx.y; r < 32; r += 8)
        tile[r][threadIdx.x] = W[(size_t)(k0 + r) * DD + n0 + threadIdx.x];
    __syncthreads();
    float* dst = g_wt[blockIdx.z];
    for (int r = threadIdx.y; r < 32; r += 8)
        dst[(size_t)(n0 + r) * DD + k0 + threadIdx.x] =
            __uint_as_float(to_tf32(tile[threadIdx.x][r]));
}

// ---------------- kernel 1: fused energy GEMM (tf32 MMA + cp.async + ldmatrix) ----------------
__device__ __forceinline__ void mma_tf32(float* c, const uint32_t* a, const uint32_t* b) {
    asm volatile(
        "mma.sync.aligned.m16n8k8.row.col.f32.tf32.tf32.f32 "
        "{%0,%1,%2,%3}, {%4,%5,%6,%7}, {%8,%9}, {%0,%1,%2,%3};\n"
        : "+f"(c[0]), "+f"(c[1]), "+f"(c[2]), "+f"(c[3])
        : "r"(a[0]), "r"(a[1]), "r"(a[2]), "r"(a[3]), "r"(b[0]), "r"(b[1]));
}

__device__ __forceinline__ void ldsm4(uint32_t* r, uint32_t addr) {
    asm volatile("ldmatrix.sync.aligned.m8n8.x4.shared.b16 {%0,%1,%2,%3}, [%4];"
        : "=r"(r[0]), "=r"(r[1]), "=r"(r[2]), "=r"(r[3]) : "r"(addr));
}

__device__ __forceinline__ void cp16(uint32_t dst, const void* src) {
    asm volatile("cp.async.cg.shared.global [%0], [%1], 16;" :: "r"(dst), "l"(src));
}

#define AS_BUF 4096   // 128 rows x 32 floats (swizzled), per stage
#define BS_BUF 4096
#define SMEM_FLOATS (2 * AS_BUF + 2 * BS_BUF)   // 16384 floats = 64 KB

// grid (8 colchunks, 500 rowblocks), 256 threads (8 warps: 4 M x 2 N)
// block tile 128M x 128N, warp tile 32M x 64N, K-block 32, 2-stage cp.async, ldmatrix frags
__global__ __launch_bounds__(256, 2) void energy_kernel(
    const float* __restrict__ key, const float* __restrict__ vchunk) {
    extern __shared__ float smem[];
    float* As = smem;                 // [2][128][32] swizzled
    float* Bs = smem + 2 * AS_BUF;    // [2][128][32] swizzled, n-major

    int tid  = threadIdx.x;
    int lane = tid & 31, wid = tid >> 5;
    int g = lane >> 2, q = lane & 3;
    int lmrow = lane & 7, lmm = lane >> 3;       // ldmatrix row-in-matrix / matrix id
    int warp_m = wid & 3, warp_n = wid >> 2;
    int row0 = blockIdx.y * 128;
    int cc = blockIdx.x;
    int mat = cc >> 2;
    int a0 = (cc & 3) * 128;
    const float* Wt = g_wt[mat];

    // cp.async tiling: thread -> (row tid>>3, chunk tid&7), 4 row-phases of 32
    int cm = tid >> 3, cck = tid & 7;
    int cphys = cck ^ (cm & 7);
    uint32_t as_base = (uint32_t)__cvta_generic_to_shared(As);
    uint32_t bs_base = (uint32_t)__cvta_generic_to_shared(Bs);

    float acc[2][8][4];
    #pragma unroll
    for (int mi = 0; mi < 2; mi++)
        #pragma unroll
        for (int ni = 0; ni < 8; ni++)
            #pragma unroll
            for (int x = 0; x < 4; x++) acc[mi][ni][x] = 0.f;

    #define PREFETCH(kb, bufp) do {                                             \
        int kbase = (kb) * 32;                                                  \
        _Pragma("unroll")                                                       \
        for (int p = 0; p < 4; p++) {                                           \
            int m = cm + p * 32;                                                \
            cp16(as_base + (uint32_t)(((bufp) * AS_BUF + m * 32 + cphys * 4) * 4), \
                 key + (size_t)(row0 + m) * 512 + kbase + cck * 4);             \
        }                                                                       \
        _Pragma("unroll")                                                       \
        for (int p = 0; p < 4; p++) {                                           \
            int n = cm + p * 32;                                                \
            cp16(bs_base + (uint32_t)(((bufp) * BS_BUF + n * 32 + cphys * 4) * 4), \
                 Wt + (size_t)(a0 + n) * 512 + kbase + cck * 4);                \
        }                                                                       \
        asm volatile("cp.async.commit_group;");                                 \
    } while (0)

    PREFETCH(0, 0);

    for (int kb = 0; kb < 16; kb++) {
        int buf = kb & 1;
        if (kb + 1 < 16) {
            PREFETCH(kb + 1, buf ^ 1);
            asm volatile("cp.async.wait_group 1;");
        } else {
            asm volatile("cp.async.wait_group 0;");
        }
        __syncthreads();

        #pragma unroll
        for (int ks = 0; ks < 4; ks++) {
            uint32_t afr[2][4];
            #pragma unroll
            for (int mi = 0; mi < 2; mi++) {
                int row = warp_m * 32 + mi * 16 + ((lmm & 1) << 3) + lmrow;
                int phys = (ks * 2 + (lmm >> 1)) ^ lmrow;
                ldsm4(afr[mi], as_base + (uint32_t)(((buf) * AS_BUF + row * 32 + phys * 4) * 4));
                #pragma unroll
                for (int j = 0; j < 4; j++)
                    afr[mi][j] = to_tf32(fmaxf(__uint_as_float(afr[mi][j]), 0.f));  // relu
            }
            uint32_t bfr[4][4];
            #pragma unroll
            for (int nb = 0; nb < 4; nb++) {
                int row = warp_n * 64 + nb * 16 + ((lmm >> 1) << 3) + lmrow;
                int phys = (ks * 2 + (lmm & 1)) ^ lmrow;
                ldsm4(bfr[nb], bs_base + (uint32_t)(((buf) * BS_BUF + row * 32 + phys * 4) * 4));
            }
            #pragma unroll
            for (int ni = 0; ni < 8; ni++) {
                mma_tf32(acc[0][ni], afr[0], &bfr[ni >> 1][(ni & 1) * 2]);
                mma_tf32(acc[1][ni], afr[1], &bfr[ni >> 1][(ni & 1) * 2]);
            }
        }
        __syncthreads();
    }

    // epilogue: e_partial(row) = sum_a tanh(acc + qb[b][a]) * v[a]
    const float* qbp = mat ? &g_qb_chunk[0][0] : &g_qb_mono[0][0];
    const float* vp  = mat ? vchunk : g_vm;
    float* eout      = mat ? g_echunk : g_emono;
    float (*red)[9]  = (float(*)[9])smem;  // 128 x 9 overlay

    #pragma unroll
    for (int mi = 0; mi < 2; mi++) {
        #pragma unroll
        for (int half = 0; half < 2; half++) {
            int lr = warp_m * 32 + mi * 16 + half * 8 + g;
            int b  = (row0 + lr) / TT;
            const float* qb = qbp + b * DD + a0;
            float s = 0.f;
            #pragma unroll
            for (int ni = 0; ni < 8; ni++) {
                int n = warp_n * 64 + ni * 8 + 2 * q;
                float c0 = acc[mi][ni][half * 2 + 0];
                float c1 = acc[mi][ni][half * 2 + 1];
                s = fmaf(tanhf(c0 + qb[n]),     vp[a0 + n],     s);
                s = fmaf(tanhf(c1 + qb[n + 1]), vp[a0 + n + 1], s);
            }
            red[lr][warp_n * 4 + q] = s;
        }
    }
    __syncthreads();
    if (tid < 128) {
        float s = 0.f;
        #pragma unroll
        for (int x = 0; x < 8; x++) s += red[tid][x];
        atomicAdd(&eout[row0 + tid], s);
    }
    #undef PREFETCH
}

// ---------------- kernel 2: noise + p + alpha scan ----------------
__global__ void mono_scan_kernel(const int* __restrict__ mask,
                                 const float* __restrict__ rmono,
                                 float* __restrict__ out_alpha) {
    int b = blockIdx.x, tid = threadIdx.x;  // 256 threads
    __shared__ float lp[TT];
    __shared__ float pp[TT];
    __shared__ float ws[8];
    float r = rmono[0];
    const int CH = 16;
    int t0 = tid * CH, t1 = min(t0 + CH, TT);
    float s = 0.f;
    for (int t = t0; t < t1; t++) {
        int i = b * TT + t;
        float e = g_emono[i] + r;
        if (mask[i] == 0) e = NEG_INF;
        float x = e + jax_normal_123(i);
        float p = 1.f / (1.f + expf(-x));
        float l = logf(fminf(fmaxf(1.f - p, EPSF), 1.f));
        pp[t] = p; lp[t] = l; s += l;
    }
    float run = block_excl_scan(s, tid, 256, ws);
    for (int t = t0; t < t1; t++) {
        float al = pp[t] * expf(run);   // exclusive cumsum -> cumprod
        run += lp[t];
        g_alpha[b * TT + t] = al;
        out_alpha[b * TT + t] = al;
    }
}

// ---------------- kernel 3: chunk energies -> beta ----------------
__global__ void chunk_post_kernel(const int* __restrict__ mask) {
    int b = blockIdx.x, tid = threadIdx.x;  // 256 threads
    __shared__ float se[TT];
    __shared__ float pref[TT];
    __shared__ float qp[TT];
    __shared__ float sh[257];

    float mx = -3.4e38f;
    for (int t = tid; t < TT; t += 256) {
        float e = g_echunk[b * TT + t];
        if (mask[b * TT + t] == 0) e = NEG_INF;
        se[t] = e;
        mx = fmaxf(mx, e);
    }
    sh[tid] = mx;
    __syncthreads();
    for (int off = 128; off > 0; off >>= 1) {
        if (tid < off) sh[tid] = fmaxf(sh[tid], sh[tid + off]);
        __syncthreads();
    }
    mx = sh[0];
    __syncthreads();

    for (int t = tid; t < TT; t += 256) se[t] = fmaxf(expf(se[t] - mx), 1e-5f);

    const int CH = 16;
    int t0 = tid * CH, t1 = min(t0 + CH, TT);
    __syncthreads();
    {
        float s = 0.f;
        for (int t = t0; t < t1; t++) s += se[t];
        float run = block_excl_scan(s, tid, 256, sh);
        for (int t = t0; t < t1; t++) { run += se[t]; pref[t] = run; }
    }
    __syncthreads();

    for (int t = tid; t < TT; t += 256) {
        float denom = pref[t] - ((t >= 8) ? pref[t - 8] : 0.f);
        qp[t] = g_alpha[b * TT + t] / denom;   // TEMP = 1
    }
    __syncthreads();

    {
        float s = 0.f;
        for (int t = t0; t < t1; t++) s += qp[t];
        float run = block_excl_scan(s, tid, 256, sh);
        for (int t = t0; t < t1; t++) { run += qp[t]; qp[t] = run; }
    }
    __syncthreads();

    for (int t = tid; t < TT; t += 256) {
        int hi = min(t + 7, TT - 1);
        float ms2 = qp[hi] - ((t > 0) ? qp[t - 1] : 0.f);
        g_beta[b * TT + t] = se[t] * ms2;
    }
}

// ---------------- kernel 4: cv = sum_t beta * value ----------------
__global__ void cv_kernel(const float* __restrict__ value, float* __restrict__ out_cv) {
    int tc = blockIdx.x;   // 32 chunks of 125
    int b  = blockIdx.y;
    int d  = threadIdx.x;  // 512
    float acc = 0.f;
    int t0 = tc * 125;
    for (int t = t0; t < t0 + 125; t++) {
        int row = b * TT + t;
        acc = fmaf(g_beta[row], value[(size_t)row * 512 + d], acc);
    }
    atomicAdd(&out_cv[b * 512 + d], acc);
}

// ---------------- launch ----------------
extern "C" void kernel_launch(void* const* d_in, const int* in_sizes, int n_in,
                              void* d_out, int out_size) {
    const float* key    = (const float*)d_in[0];
    const float* value  = (const float*)d_in[1];
    const float* query  = (const float*)d_in[2];
    const int*   mask   = (const int*)  d_in[3];
    const float* wkm    = (const float*)d_in[4];
    const float* bkm    = (const float*)d_in[5];
    const float* wqm    = (const float*)d_in[6];
    const float* vmono  = (const float*)d_in[7];
    const float* gmono  = (const float*)d_in[8];
    const float* rmono  = (const float*)d_in[9];
    const float* wkc    = (const float*)d_in[10];
    const float* bkc    = (const float*)d_in[11];
    const float* wqc    = (const float*)d_in[12];
    const float* vchunk = (const float*)d_in[13];

    float* out       = (float*)d_out;
    float* out_cv    = out;            // [16, 1, 512] first
    float* out_alpha = out + BB * DD;  // [16, 4000, 1] second

    const int smem_bytes = SMEM_FLOATS * 4;  // 65536
    cudaFuncSetAttribute(energy_kernel, cudaFuncAttributeMaxDynamicSharedMemorySize, smem_bytes);

    prep_kernel<<<64, 512>>>(query, wqm, bkm, wqc, bkc, vmono, gmono, out_cv);
    wt_kernel<<<dim3(16, 16, 2), dim3(32, 8)>>>(wkm, wkc);
    energy_kernel<<<dim3(8, 500), 256, smem_bytes>>>(key, vchunk);
    mono_scan_kernel<<<16, 256>>>(mask, rmono, out_alpha);
    chunk_post_kernel<<<16, 256>>>(mask);
    cv_kernel<<<dim3(32, 16), 512>>>(value, out_cv);
}

// round 13
// speedup vs baseline: 3.5109x; 1.0134x over previous
#include <cuda_runtime.h>
#include <cstdint>

#define BB 16
#define TT 4000
#define DD 512
#define BT (BB*TT)
#define NEG_INF (-3.4028234663852886e+38f)
#define EPSF 1e-6f

// ---------------- scratch (device globals; no allocation) ----------------
__device__ float g_qb_mono[BB][DD];
__device__ float g_qb_chunk[BB][DD];
__device__ float g_vm[DD];
__device__ float g_emono[BT];
__device__ float g_echunk[BT];
__device__ float g_alpha[BT];
__device__ float g_beta[BT];
__device__ float g_wt[2][DD * DD];   // transposed + tf32-rounded weights, [mat][n][k]

// ---------------- JAX threefry2x32 (partitionable path) + XLA erfinv ----------------
__device__ __forceinline__ uint32_t rotl32(uint32_t x, uint32_t r) {
    return (x << r) | (x >> (32u - r));
}

__device__ __forceinline__ float erfinv_xla(float x) {
    float w = -log1pf(-x * x);
    float p;
    if (w < 5.0f) {
        w = w - 2.5f;
        p = 2.81022636e-08f;
        p = fmaf(p, w, 3.43273939e-07f);
        p = fmaf(p, w, -3.5233877e-06f);
        p = fmaf(p, w, -4.39150654e-06f);
        p = fmaf(p, w, 0.00021858087f);
        p = fmaf(p, w, -0.00125372503f);
        p = fmaf(p, w, -0.00417768164f);
        p = fmaf(p, w, 0.246640727f);
        p = fmaf(p, w, 1.50140941f);
    } else {
        w = sqrtf(w) - 3.0f;
        p = -0.000200214257f;
        p = fmaf(p, w, 0.000100950558f);
        p = fmaf(p, w, 0.00134934322f);
        p = fmaf(p, w, -0.00367342844f);
        p = fmaf(p, w, 0.00573950773f);
        p = fmaf(p, w, -0.0076224613f);
        p = fmaf(p, w, 0.00943887047f);
        p = fmaf(p, w, 1.00167406f);
        p = fmaf(p, w, 2.83297682f);
    }
    return p * x;
}

// noise[i] for flattened index i in [0, 64000), key = jax.random.key(123)
// JAX >= 0.4.36 default: jax_threefry_partitionable=True
__device__ float jax_normal_123(int i) {
    const uint32_t k0 = 0u, k1 = 123u;
    const uint32_t k2 = k0 ^ k1 ^ 0x1BD11BDAu;
    uint32_t x0 = k0;
    uint32_t x1 = (uint32_t)i + k1;

    #pragma unroll
    for (int r = 0; r < 4; r++) { const uint32_t ra[4] = {13,15,26,6};
        x0 += x1; x1 = rotl32(x1, ra[r]); x1 ^= x0; }
    x0 += k1; x1 += k2 + 1u;
    #pragma unroll
    for (int r = 0; r < 4; r++) { const uint32_t rb[4] = {17,29,16,24};
        x0 += x1; x1 = rotl32(x1, rb[r]); x1 ^= x0; }
    x0 += k2; x1 += k0 + 2u;
    #pragma unroll
    for (int r = 0; r < 4; r++) { const uint32_t ra[4] = {13,15,26,6};
        x0 += x1; x1 = rotl32(x1, ra[r]); x1 ^= x0; }
    x0 += k0; x1 += k1 + 3u;
    #pragma unroll
    for (int r = 0; r < 4; r++) { const uint32_t rb[4] = {17,29,16,24};
        x0 += x1; x1 = rotl32(x1, rb[r]); x1 ^= x0; }
    x0 += k1; x1 += k2 + 4u;
    #pragma unroll
    for (int r = 0; r < 4; r++) { const uint32_t ra[4] = {13,15,26,6};
        x0 += x1; x1 = rotl32(x1, ra[r]); x1 ^= x0; }
    x0 += k2; x1 += k0 + 5u;

    uint32_t bits = x0 ^ x1;
    float f = __uint_as_float((bits >> 9) | 0x3f800000u) - 1.0f;  // [0,1)
    const float lo = -0.99999994f;
    float scale = __fsub_rn(1.0f, lo);             // == 2.0f
    float u = __fadd_rn(__fmul_rn(f, scale), lo);
    u = fmaxf(lo, u);
    return 1.41421356237f * erfinv_xla(u);
}

// ---------------- shfl-based block exclusive scan ----------------
__device__ __forceinline__ float block_excl_scan(float v, int tid, int nthreads, float* ws) {
    __syncthreads();                    // protect ws reuse
    int lane = tid & 31, w = tid >> 5, nw = nthreads >> 5;
    float x = v;
    #pragma unroll
    for (int o = 1; o < 32; o <<= 1) {
        float y = __shfl_up_sync(0xffffffffu, x, o);
        if (lane >= o) x += y;
    }
    if (lane == 31) ws[w] = x;
    __syncthreads();
    if (w == 0) {
        float s = (lane < nw) ? ws[lane] : 0.f;
        float xs = s;
        #pragma unroll
        for (int o = 1; o < 32; o <<= 1) {
            float y = __shfl_up_sync(0xffffffffu, xs, o);
            if (lane >= o) xs += y;
        }
        if (lane < nw) ws[lane] = xs - s;   // exclusive warp sums
    }
    __syncthreads();
    return ws[w] + (x - v);                 // block-exclusive prefix for this thread
}

// ---------------- kernel 0: prep ----------------
__global__ void prep_kernel(const float* __restrict__ query,
                            const float* __restrict__ wqm, const float* __restrict__ bkm,
                            const float* __restrict__ wqc, const float* __restrict__ bkc,
                            const float* __restrict__ vmono, const float* __restrict__ gmono,
                            float* __restrict__ out_cv) {
    int blk = blockIdx.x, tid = threadIdx.x;  // 512 threads
    if (blk < 32) {
        int mat = blk >> 4, b = blk & 15;
        const float* wq   = mat ? wqc : wqm;
        const float* bias = mat ? bkc : bkm;
        const float* q = query + b * DD;
        float s = bias[tid];
        for (int k = 0; k < DD; k++) s = fmaf(q[k], wq[k * DD + tid], s);
        if (mat) g_qb_chunk[b][tid] = s; else g_qb_mono[b][tid] = s;
    } else if (blk == 32) {
        __shared__ float red[512];
        float v = vmono[tid];
        red[tid] = v * v;
        __syncthreads();
        for (int off = 256; off > 0; off >>= 1) {
            if (tid < off) red[tid] += red[tid + off];
            __syncthreads();
        }
        float nrm = sqrtf(red[0]);
        g_vm[tid] = gmono[0] * vmono[tid] / nrm;
    } else {
        int nb = gridDim.x - 33, bi = blk - 33;
        for (int i = bi * 512 + tid; i < 2 * BT; i += nb * 512) {
            if (i < BT) g_emono[i] = 0.f; else g_echunk[i - BT] = 0.f;
        }
        for (int i = bi * 512 + tid; i < BB * DD; i += nb * 512) out_cv[i] = 0.f;
    }
}

// ---------------- kernel 0b: weight transpose + tf32 pre-round ----------------
__device__ __forceinline__ uint32_t to_tf32(float v) {
    uint32_t t;
    asm("cvt.rna.tf32.f32 %0, %1;" : "=r"(t) : "f"(v));
    return t;
}

__global__ void wt_kernel(const float* __restrict__ wm, const float* __restrict__ wc) {
    __shared__ float tile[32][33];
    const float* W = blockIdx.z ? wc : wm;
    int k0 = blockIdx.x * 32, n0 = blockIdx.y * 32;
    for (int r = threadIdx.y; r < 32; r += 8)
        tile[r][threadIdx.x] = W[(size_t)(k0 + r) * DD + n0 + threadIdx.x];
    __syncthreads();
    float* dst = g_wt[blockIdx.z];
    for (int r = threadIdx.y; r < 32; r += 8)
        dst[(size_t)(n0 + r) * DD + k0 + threadIdx.x] =
            __uint_as_float(to_tf32(tile[threadIdx.x][r]));
}

// ---------------- kernel 1: fused energy GEMM (tf32 MMA + 3-stage cp.async + ldmatrix) ----------------
__device__ __forceinline__ void mma_tf32(float* c, const uint32_t* a, const uint32_t* b) {
    asm volatile(
        "mma.sync.aligned.m16n8k8.row.col.f32.tf32.tf32.f32 "
        "{%0,%1,%2,%3}, {%4,%5,%6,%7}, {%8,%9}, {%0,%1,%2,%3};\n"
        : "+f"(c[0]), "+f"(c[1]), "+f"(c[2]), "+f"(c[3])
        : "r"(a[0]), "r"(a[1]), "r"(a[2]), "r"(a[3]), "r"(b[0]), "r"(b[1]));
}

__device__ __forceinline__ void ldsm4(uint32_t* r, uint32_t addr) {
    asm volatile("ldmatrix.sync.aligned.m8n8.x4.shared.b16 {%0,%1,%2,%3}, [%4];"
        : "=r"(r[0]), "=r"(r[1]), "=r"(r[2]), "=r"(r[3]) : "r"(addr));
}

__device__ __forceinline__ void cp16(uint32_t dst, const void* src) {
    asm volatile("cp.async.cg.shared.global [%0], [%1], 16;" :: "r"(dst), "l"(src));
}

#define AS_BUF 4096                       // 128 rows x 32 floats (swizzled)
#define STAGE_F 8192                      // A + B per stage
#define NSTAGE 3
#define SMEM_FLOATS (NSTAGE * STAGE_F)    // 24576 floats = 96 KB

// grid (8 colchunks, 500 rowblocks), 256 threads (8 warps: 4 M x 2 N)
// block tile 128M x 128N, warp tile 32M x 64N, K-block 32, 3-stage cp.async, ldmatrix frags
__global__ __launch_bounds__(256, 2) void energy_kernel(
    const float* __restrict__ key, const float* __restrict__ vchunk) {
    extern __shared__ float smem[];

    int tid  = threadIdx.x;
    int lane = tid & 31, wid = tid >> 5;
    int g = lane >> 2, q = lane & 3;
    int lmrow = lane & 7, lmm = lane >> 3;       // ldmatrix row-in-matrix / matrix id
    int warp_m = wid & 3, warp_n = wid >> 2;
    int row0 = blockIdx.y * 128;
    int cc = blockIdx.x;
    int mat = cc >> 2;
    int a0 = (cc & 3) * 128;
    const float* Wt = g_wt[mat];

    // cp.async tiling: thread -> (row tid>>3, chunk tid&7), 4 row-phases of 32
    int cm = tid >> 3, cck = tid & 7;
    int cphys = cck ^ (cm & 7);
    uint32_t sbase = (uint32_t)__cvta_generic_to_shared(smem);

    float acc[2][8][4];
    #pragma unroll
    for (int mi = 0; mi < 2; mi++)
        #pragma unroll
        for (int ni = 0; ni < 8; ni++)
            #pragma unroll
            for (int x = 0; x < 4; x++) acc[mi][ni][x] = 0.f;

    #define PREFETCH(kb, st) do {                                               \
        int kbase = (kb) * 32;                                                  \
        uint32_t abuf = sbase + (uint32_t)((st) * STAGE_F * 4);                 \
        _Pragma("unroll")                                                       \
        for (int p = 0; p < 4; p++) {                                           \
            int m = cm + p * 32;                                                \
            cp16(abuf + (uint32_t)((m * 32 + cphys * 4) * 4),                   \
                 key + (size_t)(row0 + m) * 512 + kbase + cck * 4);             \
        }                                                                       \
        _Pragma("unroll")                                                       \
        for (int p = 0; p < 4; p++) {                                           \
            int n = cm + p * 32;                                                \
            cp16(abuf + (uint32_t)((AS_BUF + n * 32 + cphys * 4) * 4),          \
                 Wt + (size_t)(a0 + n) * 512 + kbase + cck * 4);                \
        }                                                                       \
        asm volatile("cp.async.commit_group;");                                 \
    } while (0)

    PREFETCH(0, 0);
    PREFETCH(1, 1);

    int scur = 0;   // stage holding K-block kb
    for (int kb = 0; kb < 16; kb++) {
        if (kb + 1 < 16) {
            asm volatile("cp.async.wait_group 1;");
        } else {
            asm volatile("cp.async.wait_group 0;");
        }
        __syncthreads();   // stage scur visible to all; stage (kb-1)%3 fully consumed

        if (kb + 2 < 16) {
            int spre = (scur == 0) ? 2 : scur - 1;   // (kb+2)%3 == (kb-1)%3
            PREFETCH(kb + 2, spre);
        }

        uint32_t abase = sbase + (uint32_t)(scur * STAGE_F * 4);
        uint32_t bbase = abase + (uint32_t)(AS_BUF * 4);
        #pragma unroll
        for (int ks = 0; ks < 4; ks++) {
            uint32_t afr[2][4];
            #pragma unroll
            for (int mi = 0; mi < 2; mi++) {
                int row = warp_m * 32 + mi * 16 + ((lmm & 1) << 3) + lmrow;
                int phys = (ks * 2 + (lmm >> 1)) ^ lmrow;
                ldsm4(afr[mi], abase + (uint32_t)((row * 32 + phys * 4) * 4));
                #pragma unroll
                for (int j = 0; j < 4; j++)
                    afr[mi][j] = to_tf32(fmaxf(__uint_as_float(afr[mi][j]), 0.f));  // relu
            }
            uint32_t bfr[4][4];
            #pragma unroll
            for (int nb = 0; nb < 4; nb++) {
                int row = warp_n * 64 + nb * 16 + ((lmm >> 1) << 3) + lmrow;
                int phys = (ks * 2 + (lmm & 1)) ^ lmrow;
                ldsm4(bfr[nb], bbase + (uint32_t)((row * 32 + phys * 4) * 4));
            }
            #pragma unroll
            for (int ni = 0; ni < 8; ni++) {
                mma_tf32(acc[0][ni], afr[0], &bfr[ni >> 1][(ni & 1) * 2]);
                mma_tf32(acc[1][ni], afr[1], &bfr[ni >> 1][(ni & 1) * 2]);
            }
        }
        scur = (scur == 2) ? 0 : scur + 1;
    }
    __syncthreads();   // done with smem tiles before epilogue overlay

    // epilogue: e_partial(row) = sum_a tanh(acc + qb[b][a]) * v[a]
    const float* qbp = mat ? &g_qb_chunk[0][0] : &g_qb_mono[0][0];
    const float* vp  = mat ? vchunk : g_vm;
    float* eout      = mat ? g_echunk : g_emono;
    float (*red)[9]  = (float(*)[9])smem;  // 128 x 9 overlay

    #pragma unroll
    for (int mi = 0; mi < 2; mi++) {
        #pragma unroll
        for (int half = 0; half < 2; half++) {
            int lr = warp_m * 32 + mi * 16 + half * 8 + g;
            int b  = (row0 + lr) / TT;
            const float* qb = qbp + b * DD + a0;
            float s = 0.f;
            #pragma unroll
            for (int ni = 0; ni < 8; ni++) {
                int n = warp_n * 64 + ni * 8 + 2 * q;
                float c0 = acc[mi][ni][half * 2 + 0];
                float c1 = acc[mi][ni][half * 2 + 1];
                s = fmaf(tanhf(c0 + qb[n]),     vp[a0 + n],     s);
                s = fmaf(tanhf(c1 + qb[n + 1]), vp[a0 + n + 1], s);
            }
            red[lr][warp_n * 4 + q] = s;
        }
    }
    __syncthreads();
    if (tid < 128) {
        float s = 0.f;
        #pragma unroll
        for (int x = 0; x < 8; x++) s += red[tid][x];
        atomicAdd(&eout[row0 + tid], s);
    }
    #undef PREFETCH
}

// ---------------- kernel 2: noise + p + alpha scan ----------------
__global__ void mono_scan_kernel(const int* __restrict__ mask,
                                 const float* __restrict__ rmono,
                                 float* __restrict__ out_alpha) {
    int b = blockIdx.x, tid = threadIdx.x;  // 512 threads
    __shared__ float lp[TT];
    __shared__ float pp[TT];
    __shared__ float ws[16];
    float r = rmono[0];
    const int CH = 8;   // ceil(4000/512)
    int t0 = tid * CH, t1 = min(t0 + CH, TT);
    float s = 0.f;
    for (int t = t0; t < t1; t++) {
        int i = b * TT + t;
        float e = g_emono[i] + r;
        if (mask[i] == 0) e = NEG_INF;
        float x = e + jax_normal_123(i);
        float p = 1.f / (1.f + expf(-x));
        float l = logf(fminf(fmaxf(1.f - p, EPSF), 1.f));
        pp[t] = p; lp[t] = l; s += l;
    }
    float run = block_excl_scan(s, tid, 512, ws);
    for (int t = t0; t < t1; t++) {
        float al = pp[t] * expf(run);   // exclusive cumsum -> cumprod
        run += lp[t];
        g_alpha[b * TT + t] = al;
        out_alpha[b * TT + t] = al;
    }
}

// ---------------- kernel 3: chunk energies -> beta ----------------
__global__ void chunk_post_kernel(const int* __restrict__ mask) {
    int b = blockIdx.x, tid = threadIdx.x;  // 512 threads
    __shared__ float se[TT];
    __shared__ float pref[TT];
    __shared__ float qp[TT];
    __shared__ float sh[512];

    float mx = -3.4e38f;
    for (int t = tid; t < TT; t += 512) {
        float e = g_echunk[b * TT + t];
        if (mask[b * TT + t] == 0) e = NEG_INF;
        se[t] = e;
        mx = fmaxf(mx, e);
    }
    sh[tid] = mx;
    __syncthreads();
    for (int off = 256; off > 0; off >>= 1) {
        if (tid < off) sh[tid] = fmaxf(sh[tid], sh[tid + off]);
        __syncthreads();
    }
    mx = sh[0];
    __syncthreads();

    for (int t = tid; t < TT; t += 512) se[t] = fmaxf(expf(se[t] - mx), 1e-5f);

    const int CH = 8;
    int t0 = tid * CH, t1 = min(t0 + CH, TT);
    __syncthreads();
    {
        float s = 0.f;
        for (int t = t0; t < t1; t++) s += se[t];
        float run = block_excl_scan(s, tid, 512, sh);
        for (int t = t0; t < t1; t++) { run += se[t]; pref[t] = run; }
    }
    __syncthreads();

    for (int t = tid; t < TT; t += 512) {
        float denom = pref[t] - ((t >= 8) ? pref[t - 8] : 0.f);
        qp[t] = g_alpha[b * TT + t] / denom;   // TEMP = 1
    }
    __syncthreads();

    {
        float s = 0.f;
        for (int t = t0; t < t1; t++) s += qp[t];
        float run = block_excl_scan(s, tid, 512, sh);
        for (int t = t0; t < t1; t++) { run += qp[t]; qp[t] = run; }
    }
    __syncthreads();

    for (int t = tid; t < TT; t += 512) {
        int hi = min(t + 7, TT - 1);
        float ms2 = qp[hi] - ((t > 0) ? qp[t - 1] : 0.f);
        g_beta[b * TT + t] = se[t] * ms2;
    }
}

// ---------------- kernel 4: cv = sum_t beta * value ----------------
__global__ void cv_kernel(const float* __restrict__ value, float* __restrict__ out_cv) {
    int tc = blockIdx.x;   // 32 chunks of 125
    int b  = blockIdx.y;
    int d  = threadIdx.x;  // 512
    float acc = 0.f;
    int t0 = tc * 125;
    for (int t = t0; t < t0 + 125; t++) {
        int row = b * TT + t;
        acc = fmaf(g_beta[row], value[(size_t)row * 512 + d], acc);
    }
    atomicAdd(&out_cv[b * 512 + d], acc);
}

// ---------------- launch ----------------
extern "C" void kernel_launch(void* const* d_in, const int* in_sizes, int n_in,
                              void* d_out, int out_size) {
    const float* key    = (const float*)d_in[0];
    const float* value  = (const float*)d_in[1];
    const float* query  = (const float*)d_in[2];
    const int*   mask   = (const int*)  d_in[3];
    const float* wkm    = (const float*)d_in[4];
    const float* bkm    = (const float*)d_in[5];
    const float* wqm    = (const float*)d_in[6];
    const float* vmono  = (const float*)d_in[7];
    const float* gmono  = (const float*)d_in[8];
    const float* rmono  = (const float*)d_in[9];
    const float* wkc    = (const float*)d_in[10];
    const float* bkc    = (const float*)d_in[11];
    const float* wqc    = (const float*)d_in[12];
    const float* vchunk = (const float*)d_in[13];

    float* out       = (float*)d_out;
    float* out_cv    = out;            // [16, 1, 512] first
    float* out_alpha = out + BB * DD;  // [16, 4000, 1] second

    const int smem_bytes = SMEM_FLOATS * 4;  // 98304 (96 KB)
    cudaFuncSetAttribute(energy_kernel, cudaFuncAttributeMaxDynamicSharedMemorySize, smem_bytes);

    prep_kernel<<<64, 512>>>(query, wqm, bkm, wqc, bkc, vmono, gmono, out_cv);
    wt_kernel<<<dim3(16, 16, 2), dim3(32, 8)>>>(wkm, wkc);
    energy_kernel<<<dim3(8, 500), 256, smem_bytes>>>(key, vchunk);
    mono_scan_kernel<<<16, 512>>>(mask, rmono, out_alpha);
    chunk_post_kernel<<<16, 512>>>(mask);
    cv_kernel<<<dim3(32, 16), 512>>>(value, out_cv);
}

// round 16
// speedup vs baseline: 4.8297x; 1.3756x over previous
#include <cuda_runtime.h>
#include <cuda_fp16.h>
#include <cstdint>

#define BB 16
#define TT 4000
#define DD 512
#define BT (BB*TT)
#define NEG_INF (-3.4028234663852886e+38f)
#define EPSF 1e-6f

// ---------------- scratch (device globals; no allocation) ----------------
__device__ float g_qb_mono[BB][DD];
__device__ float g_qb_chunk[BB][DD];
__device__ float g_vm[DD];
__device__ float g_emono[BT];
__device__ float g_echunk[BT];
__device__ float g_alpha[BT];
__device__ float g_beta[BT];
__device__ __half g_wth[2][DD * DD];            // W^T as fp16, [mat][n][k]
__device__ __half g_keyh[(size_t)BT * DD];      // half(relu(key))

// ---------------- JAX threefry2x32 (partitionable path) + XLA erfinv ----------------
__device__ __forceinline__ uint32_t rotl32(uint32_t x, uint32_t r) {
    return (x << r) | (x >> (32u - r));
}

__device__ __forceinline__ float erfinv_xla(float x) {
    float w = -log1pf(-x * x);
    float p;
    if (w < 5.0f) {
        w = w - 2.5f;
        p = 2.81022636e-08f;
        p = fmaf(p, w, 3.43273939e-07f);
        p = fmaf(p, w, -3.5233877e-06f);
        p = fmaf(p, w, -4.39150654e-06f);
        p = fmaf(p, w, 0.00021858087f);
        p = fmaf(p, w, -0.00125372503f);
        p = fmaf(p, w, -0.00417768164f);
        p = fmaf(p, w, 0.246640727f);
        p = fmaf(p, w, 1.50140941f);
    } else {
        w = sqrtf(w) - 3.0f;
        p = -0.000200214257f;
        p = fmaf(p, w, 0.000100950558f);
        p = fmaf(p, w, 0.00134934322f);
        p = fmaf(p, w, -0.00367342844f);
        p = fmaf(p, w, 0.00573950773f);
        p = fmaf(p, w, -0.0076224613f);
        p = fmaf(p, w, 0.00943887047f);
        p = fmaf(p, w, 1.00167406f);
        p = fmaf(p, w, 2.83297682f);
    }
    return p * x;
}

__device__ float jax_normal_123(int i) {
    const uint32_t k0 = 0u, k1 = 123u;
    const uint32_t k2 = k0 ^ k1 ^ 0x1BD11BDAu;
    uint32_t x0 = k0;
    uint32_t x1 = (uint32_t)i + k1;

    #pragma unroll
    for (int r = 0; r < 4; r++) { const uint32_t ra[4] = {13,15,26,6};
        x0 += x1; x1 = rotl32(x1, ra[r]); x1 ^= x0; }
    x0 += k1; x1 += k2 + 1u;
    #pragma unroll
    for (int r = 0; r < 4; r++) { const uint32_t rb[4] = {17,29,16,24};
        x0 += x1; x1 = rotl32(x1, rb[r]); x1 ^= x0; }
    x0 += k2; x1 += k0 + 2u;
    #pragma unroll
    for (int r = 0; r < 4; r++) { const uint32_t ra[4] = {13,15,26,6};
        x0 += x1; x1 = rotl32(x1, ra[r]); x1 ^= x0; }
    x0 += k0; x1 += k1 + 3u;
    #pragma unroll
    for (int r = 0; r < 4; r++) { const uint32_t rb[4] = {17,29,16,24};
        x0 += x1; x1 = rotl32(x1, rb[r]); x1 ^= x0; }
    x0 += k1; x1 += k2 + 4u;
    #pragma unroll
    for (int r = 0; r < 4; r++) { const uint32_t ra[4] = {13,15,26,6};
        x0 += x1; x1 = rotl32(x1, ra[r]); x1 ^= x0; }
    x0 += k2; x1 += k0 + 5u;

    uint32_t bits = x0 ^ x1;
    float f = __uint_as_float((bits >> 9) | 0x3f800000u) - 1.0f;
    const float lo = -0.99999994f;
    float scale = __fsub_rn(1.0f, lo);
    float u = __fadd_rn(__fmul_rn(f, scale), lo);
    u = fmaxf(lo, u);
    return 1.41421356237f * erfinv_xla(u);
}

// ---------------- helpers ----------------
__device__ __forceinline__ float block_excl_scan(float v, int tid, int nthreads, float* ws) {
    __syncthreads();
    int lane = tid & 31, w = tid >> 5, nw = nthreads >> 5;
    float x = v;
    #pragma unroll
    for (int o = 1; o < 32; o <<= 1) {
        float y = __shfl_up_sync(0xffffffffu, x, o);
        if (lane >= o) x += y;
    }
    if (lane == 31) ws[w] = x;
    __syncthreads();
    if (w == 0) {
        float s = (lane < nw) ? ws[lane] : 0.f;
        float xs = s;
        #pragma unroll
        for (int o = 1; o < 32; o <<= 1) {
            float y = __shfl_up_sync(0xffffffffu, xs, o);
            if (lane >= o) xs += y;
        }
        if (lane < nw) ws[lane] = xs - s;
    }
    __syncthreads();
    return ws[w] + (x - v);
}

__device__ __forceinline__ void cp16(uint32_t dst, const void* src) {
    asm volatile("cp.async.cg.shared.global [%0], [%1], 16;" :: "r"(dst), "l"(src));
}

// ---------------- kernel 0: prep ----------------
__global__ void prep_kernel(const float* __restrict__ query,
                            const float* __restrict__ wqm, const float* __restrict__ bkm,
                            const float* __restrict__ wqc, const float* __restrict__ bkc,
                            const float* __restrict__ vmono, const float* __restrict__ gmono,
                            float* __restrict__ out_cv) {
    int blk = blockIdx.x, tid = threadIdx.x;  // 512 threads
    if (blk < 32) {
        int mat = blk >> 4, b = blk & 15;
        const float* wq   = mat ? wqc : wqm;
        const float* bias = mat ? bkc : bkm;
        const float* q = query + b * DD;
        float s = bias[tid];
        for (int k = 0; k < DD; k++) s = fmaf(q[k], wq[k * DD + tid], s);
        if (mat) g_qb_chunk[b][tid] = s; else g_qb_mono[b][tid] = s;
    } else if (blk == 32) {
        __shared__ float red[512];
        float v = vmono[tid];
        red[tid] = v * v;
        __syncthreads();
        for (int off = 256; off > 0; off >>= 1) {
            if (tid < off) red[tid] += red[tid + off];
            __syncthreads();
        }
        float nrm = sqrtf(red[0]);
        g_vm[tid] = gmono[0] * vmono[tid] / nrm;
    } else {
        int nb = gridDim.x - 33, bi = blk - 33;
        for (int i = bi * 512 + tid; i < 2 * BT; i += nb * 512) {
            if (i < BT) g_emono[i] = 0.f; else g_echunk[i - BT] = 0.f;
        }
        for (int i = bi * 512 + tid; i < BB * DD; i += nb * 512) out_cv[i] = 0.f;
    }
}

// ---------------- kernel 0b: weight transpose -> fp16 ----------------
__global__ void wt_kernel(const float* __restrict__ wm, const float* __restrict__ wc) {
    __shared__ float tile[32][33];
    const float* W = blockIdx.z ? wc : wm;
    int k0 = blockIdx.x * 32, n0 = blockIdx.y * 32;
    for (int r = threadIdx.y; r < 32; r += 8)
        tile[r][threadIdx.x] = W[(size_t)(k0 + r) * DD + n0 + threadIdx.x];
    __syncthreads();
    __half* dst = g_wth[blockIdx.z];
    for (int r = threadIdx.y; r < 32; r += 8)
        dst[(size_t)(n0 + r) * DD + k0 + threadIdx.x] = __float2half_rn(tile[threadIdx.x][r]);
}

// ---------------- kernel 0c: half(relu(key)) ----------------
__global__ void cvt_key_kernel(const float* __restrict__ key) {
    size_t i = ((size_t)blockIdx.x * 256 + threadIdx.x) * 8;
    float4 v0 = *(const float4*)(key + i);
    float4 v1 = *(const float4*)(key + i + 4);
    __half2 h0 = __floats2half2_rn(fmaxf(v0.x, 0.f), fmaxf(v0.y, 0.f));
    __half2 h1 = __floats2half2_rn(fmaxf(v0.z, 0.f), fmaxf(v0.w, 0.f));
    __half2 h2 = __floats2half2_rn(fmaxf(v1.x, 0.f), fmaxf(v1.y, 0.f));
    __half2 h3 = __floats2half2_rn(fmaxf(v1.z, 0.f), fmaxf(v1.w, 0.f));
    uint4 o;
    o.x = *(uint32_t*)&h0; o.y = *(uint32_t*)&h1;
    o.z = *(uint32_t*)&h2; o.w = *(uint32_t*)&h3;
    *(uint4*)(g_keyh + i) = o;
}

// ---------------- kernel 1: fused energy GEMM (fp16 MMA + 3-stage cp.async + ldmatrix) ----------------
__device__ __forceinline__ void mma_f16(float* c, const uint32_t* a, uint32_t b0, uint32_t b1) {
    asm volatile(
        "mma.sync.aligned.m16n8k16.row.col.f32.f16.f16.f32 "
        "{%0,%1,%2,%3}, {%4,%5,%6,%7}, {%8,%9}, {%0,%1,%2,%3};\n"
        : "+f"(c[0]), "+f"(c[1]), "+f"(c[2]), "+f"(c[3])
        : "r"(a[0]), "r"(a[1]), "r"(a[2]), "r"(a[3]), "r"(b0), "r"(b1));
}

__device__ __forceinline__ void ldsm4(uint32_t* r, uint32_t addr) {
    asm volatile("ldmatrix.sync.aligned.m8n8.x4.shared.b16 {%0,%1,%2,%3}, [%4];"
        : "=r"(r[0]), "=r"(r[1]), "=r"(r[2]), "=r"(r[3]) : "r"(addr));
}

#define A_BYTES 16384                     // 128 rows x 128B (64 halves)
#define STAGE_BYTES 32768                 // A + B
#define NSTAGE 3
#define EK_SMEM (NSTAGE * STAGE_BYTES)    // 96 KB

// grid (8 colchunks, 500 rowblocks), 256 threads (8 warps: 4 M x 2 N)
// block tile 128M x 128N, warp tile 32M x 64N, K-stage 64, 3-stage cp.async
__global__ __launch_bounds__(256, 2) void energy_kernel(const float* __restrict__ vchunk) {
    extern __shared__ __align__(128) char smem[];

    int tid  = threadIdx.x;
    int lane = tid & 31, wid = tid >> 5;
    int g = lane >> 2, q = lane & 3;
    int lmrow = lane & 7, lmm = lane >> 3;       // ldmatrix row / matrix id
    int warp_m = wid & 3, warp_n = wid >> 2;
    int row0 = blockIdx.y * 128;
    int cc = blockIdx.x;
    int mat = cc >> 2;
    int a0 = (cc & 3) * 128;
    const __half* Wt = g_wth[mat];

    // cp.async: thread -> (row tid>>3, chunk tid&7), 4 row-phases of 32
    int cm = tid >> 3, cck = tid & 7;
    uint32_t sbase = (uint32_t)__cvta_generic_to_shared(smem);

    float acc[2][8][4];
    #pragma unroll
    for (int mi = 0; mi < 2; mi++)
        #pragma unroll
        for (int ni = 0; ni < 8; ni++)
            #pragma unroll
            for (int x = 0; x < 4; x++) acc[mi][ni][x] = 0.f;

    #define PREFETCH(kb, st) do {                                               \
        int kbase = (kb) * 64;                                                  \
        uint32_t sb = sbase + (uint32_t)((st) * STAGE_BYTES);                   \
        _Pragma("unroll")                                                       \
        for (int p = 0; p < 4; p++) {                                           \
            int m = cm + p * 32; int ph = cck ^ (m & 7);                        \
            cp16(sb + (uint32_t)(m * 128 + ph * 16),                            \
                 g_keyh + (size_t)(row0 + m) * 512 + kbase + cck * 8);          \
        }                                                                       \
        _Pragma("unroll")                                                       \
        for (int p = 0; p < 4; p++) {                                           \
            int n = cm + p * 32; int ph = cck ^ (n & 7);                        \
            cp16(sb + (uint32_t)(A_BYTES + n * 128 + ph * 16),                  \
                 Wt + (size_t)(a0 + n) * 512 + kbase + cck * 8);                \
        }                                                                       \
        asm volatile("cp.async.commit_group;");                                 \
    } while (0)

    PREFETCH(0, 0);
    PREFETCH(1, 1);

    int scur = 0;
    for (int kb = 0; kb < 8; kb++) {
        if (kb + 1 < 8) asm volatile("cp.async.wait_group 1;");
        else            asm volatile("cp.async.wait_group 0;");
        __syncthreads();   // stage scur visible; stage (kb-1)%3 fully consumed

        if (kb + 2 < 8) {
            int spre = (scur == 0) ? 2 : scur - 1;   // (kb+2)%3
            PREFETCH(kb + 2, spre);
        }

        uint32_t abase = sbase + (uint32_t)(scur * STAGE_BYTES);
        uint32_t bbase = abase + A_BYTES;
        #pragma unroll
        for (int ks = 0; ks < 4; ks++) {           // k16 chunks within K=64
            int chunkL = ks * 2 + (lmm >> 1);      // 8-half chunk for this lane's matrix
            uint32_t afr[2][4];
            #pragma unroll
            for (int mi = 0; mi < 2; mi++) {
                int row = warp_m * 32 + mi * 16 + ((lmm & 1) << 3) + lmrow;
                int phys = chunkL ^ (row & 7);
                ldsm4(afr[mi], abase + (uint32_t)(row * 128 + phys * 16));
            }
            uint32_t bfr[4][4];
            #pragma unroll
            for (int nb = 0; nb < 4; nb++) {
                int row = warp_n * 64 + nb * 16 + ((lmm & 1) << 3) + lmrow;
                int phys = chunkL ^ (row & 7);
                ldsm4(bfr[nb], bbase + (uint32_t)(row * 128 + phys * 16));
            }
            #pragma unroll
            for (int nb = 0; nb < 4; nb++) {
                mma_f16(acc[0][nb * 2    ], afr[0], bfr[nb][0], bfr[nb][2]);
                mma_f16(acc[0][nb * 2 + 1], afr[0], bfr[nb][1], bfr[nb][3]);
                mma_f16(acc[1][nb * 2    ], afr[1], bfr[nb][0], bfr[nb][2]);
                mma_f16(acc[1][nb * 2 + 1], afr[1], bfr[nb][1], bfr[nb][3]);
            }
        }
        scur = (scur == 2) ? 0 : scur + 1;
    }
    __syncthreads();   // done with smem tiles before epilogue overlay

    // epilogue: e_partial(row) = sum_a tanh(acc + qb[b][a]) * v[a]
    const float* qbp = mat ? &g_qb_chunk[0][0] : &g_qb_mono[0][0];
    const float* vp  = mat ? vchunk : g_vm;
    float* eout      = mat ? g_echunk : g_emono;
    float (*red)[9]  = (float(*)[9])smem;  // 128 x 9 overlay

    #pragma unroll
    for (int mi = 0; mi < 2; mi++) {
        #pragma unroll
        for (int half = 0; half < 2; half++) {
            int lr = warp_m * 32 + mi * 16 + half * 8 + g;
            int b  = (row0 + lr) / TT;
            const float* qb = qbp + b * DD + a0;
            float s = 0.f;
            #pragma unroll
            for (int ni = 0; ni < 8; ni++) {
                int n = warp_n * 64 + ni * 8 + 2 * q;
                float c0 = acc[mi][ni][half * 2 + 0];
                float c1 = acc[mi][ni][half * 2 + 1];
                s = fmaf(tanhf(c0 + qb[n]),     vp[a0 + n],     s);
                s = fmaf(tanhf(c1 + qb[n + 1]), vp[a0 + n + 1], s);
            }
            red[lr][warp_n * 4 + q] = s;
        }
    }
    __syncthreads();
    if (tid < 128) {
        float s = 0.f;
        #pragma unroll
        for (int x = 0; x < 8; x++) s += red[tid][x];
        atomicAdd(&eout[row0 + tid], s);
    }
    #undef PREFETCH
}

// ---------------- kernel 2: noise + p + alpha scan ----------------
__global__ void mono_scan_kernel(const int* __restrict__ mask,
                                 const float* __restrict__ rmono,
                                 float* __restrict__ out_alpha) {
    int b = blockIdx.x, tid = threadIdx.x;  // 512 threads
    __shared__ float lp[TT];
    __shared__ float pp[TT];
    __shared__ float ws[16];
    float r = rmono[0];
    const int CH = 8;
    int t0 = tid * CH, t1 = min(t0 + CH, TT);
    float s = 0.f;
    for (int t = t0; t < t1; t++) {
        int i = b * TT + t;
        float e = g_emono[i] + r;
        if (mask[i] == 0) e = NEG_INF;
        float x = e + jax_normal_123(i);
        float p = 1.f / (1.f + expf(-x));
        float l = logf(fminf(fmaxf(1.f - p, EPSF), 1.f));
        pp[t] = p; lp[t] = l; s += l;
    }
    float run = block_excl_scan(s, tid, 512, ws);
    for (int t = t0; t < t1; t++) {
        float al = pp[t] * expf(run);
        run += lp[t];
        g_alpha[b * TT + t] = al;
        out_alpha[b * TT + t] = al;
    }
}

// ---------------- kernel 3: chunk energies -> beta ----------------
__global__ void chunk_post_kernel(const int* __restrict__ mask) {
    int b = blockIdx.x, tid = threadIdx.x;  // 512 threads
    __shared__ float se[TT];
    __shared__ float pref[TT];
    __shared__ float qp[TT];
    __shared__ float sh[512];

    float mx = -3.4e38f;
    for (int t = tid; t < TT; t += 512) {
        float e = g_echunk[b * TT + t];
        if (mask[b * TT + t] == 0) e = NEG_INF;
        se[t] = e;
        mx = fmaxf(mx, e);
    }
    sh[tid] = mx;
    __syncthreads();
    for (int off = 256; off > 0; off >>= 1) {
        if (tid < off) sh[tid] = fmaxf(sh[tid], sh[tid + off]);
        __syncthreads();
    }
    mx = sh[0];
    __syncthreads();

    for (int t = tid; t < TT; t += 512) se[t] = fmaxf(expf(se[t] - mx), 1e-5f);

    const int CH = 8;
    int t0 = tid * CH, t1 = min(t0 + CH, TT);
    __syncthreads();
    {
        float s = 0.f;
        for (int t = t0; t < t1; t++) s += se[t];
        float run = block_excl_scan(s, tid, 512, sh);
        for (int t = t0; t < t1; t++) { run += se[t]; pref[t] = run; }
    }
    __syncthreads();

    for (int t = tid; t < TT; t += 512) {
        float denom = pref[t] - ((t >= 8) ? pref[t - 8] : 0.f);
        qp[t] = g_alpha[b * TT + t] / denom;
    }
    __syncthreads();

    {
        float s = 0.f;
        for (int t = t0; t < t1; t++) s += qp[t];
        float run = block_excl_scan(s, tid, 512, sh);
        for (int t = t0; t < t1; t++) { run += qp[t]; qp[t] = run; }
    }
    __syncthreads();

    for (int t = tid; t < TT; t += 512) {
        int hi = min(t + 7, TT - 1);
        float ms2 = qp[hi] - ((t > 0) ? qp[t - 1] : 0.f);
        g_beta[b * TT + t] = se[t] * ms2;
    }
}

// ---------------- kernel 4: cv = sum_t beta * value ----------------
__global__ void cv_kernel(const float* __restrict__ value, float* __restrict__ out_cv) {
    int tc = blockIdx.x;
    int b  = blockIdx.y;
    int d  = threadIdx.x;
    float acc = 0.f;
    int t0 = tc * 125;
    for (int t = t0; t < t0 + 125; t++) {
        int row = b * TT + t;
        acc = fmaf(g_beta[row], value[(size_t)row * 512 + d], acc);
    }
    atomicAdd(&out_cv[b * 512 + d], acc);
}

// ---------------- launch ----------------
extern "C" void kernel_launch(void* const* d_in, const int* in_sizes, int n_in,
                              void* d_out, int out_size) {
    const float* key    = (const float*)d_in[0];
    const float* value  = (const float*)d_in[1];
    const float* query  = (const float*)d_in[2];
    const int*   mask   = (const int*)  d_in[3];
    const float* wkm    = (const float*)d_in[4];
    const float* bkm    = (const float*)d_in[5];
    const float* wqm    = (const float*)d_in[6];
    const float* vmono  = (const float*)d_in[7];
    const float* gmono  = (const float*)d_in[8];
    const float* rmono  = (const float*)d_in[9];
    const float* wkc    = (const float*)d_in[10];
    const float* bkc    = (const float*)d_in[11];
    const float* wqc    = (const float*)d_in[12];
    const float* vchunk = (const float*)d_in[13];

    float* out       = (float*)d_out;
    float* out_cv    = out;            // [16, 1, 512] first
    float* out_alpha = out + BB * DD;  // [16, 4000, 1] second

    cudaFuncSetAttribute(energy_kernel, cudaFuncAttributeMaxDynamicSharedMemorySize, EK_SMEM);

    prep_kernel<<<64, 512>>>(query, wqm, bkm, wqc, bkc, vmono, gmono, out_cv);
    wt_kernel<<<dim3(16, 16, 2), dim3(32, 8)>>>(wkm, wkc);
    cvt_key_kernel<<<(int)(((size_t)BT * DD / 8) / 256), 256>>>(key);
    energy_kernel<<<dim3(8, 500), 256, EK_SMEM>>>(vchunk);
    mono_scan_kernel<<<16, 512>>>(mask, rmono, out_alpha);
    chunk_post_kernel<<<16, 512>>>(mask);
    cv_kernel<<<dim3(32, 16), 512>>>(value, out_cv);
}

// round 17
// speedup vs baseline: 5.0476x; 1.0451x over previous
#include <cuda_runtime.h>
#include <cuda_fp16.h>
#include <cstdint>

#define BB 16
#define TT 4000
#define DD 512
#define BT (BB*TT)
#define NEG_INF (-3.4028234663852886e+38f)
#define EPSF 1e-6f

// ---------------- scratch (device globals; no allocation) ----------------
__device__ float g_qb_mono[BB][DD];
__device__ float g_qb_chunk[BB][DD];
__device__ float g_vm[DD];
__device__ float g_emono[BT];
__device__ float g_echunk[BT];
__device__ float g_beta[BT];
__device__ __half g_wth[2][DD * DD];            // W^T as fp16, [mat][n][k]
__device__ __half g_keyh[(size_t)BT * DD];      // half(relu(key))

// ---------------- JAX threefry2x32 (partitionable path) + XLA erfinv ----------------
__device__ __forceinline__ uint32_t rotl32(uint32_t x, uint32_t r) {
    return (x << r) | (x >> (32u - r));
}

__device__ __forceinline__ float erfinv_xla(float x) {
    float w = -log1pf(-x * x);
    float p;
    if (w < 5.0f) {
        w = w - 2.5f;
        p = 2.81022636e-08f;
        p = fmaf(p, w, 3.43273939e-07f);
        p = fmaf(p, w, -3.5233877e-06f);
        p = fmaf(p, w, -4.39150654e-06f);
        p = fmaf(p, w, 0.00021858087f);
        p = fmaf(p, w, -0.00125372503f);
        p = fmaf(p, w, -0.00417768164f);
        p = fmaf(p, w, 0.246640727f);
        p = fmaf(p, w, 1.50140941f);
    } else {
        w = sqrtf(w) - 3.0f;
        p = -0.000200214257f;
        p = fmaf(p, w, 0.000100950558f);
        p = fmaf(p, w, 0.00134934322f);
        p = fmaf(p, w, -0.00367342844f);
        p = fmaf(p, w, 0.00573950773f);
        p = fmaf(p, w, -0.0076224613f);
        p = fmaf(p, w, 0.00943887047f);
        p = fmaf(p, w, 1.00167406f);
        p = fmaf(p, w, 2.83297682f);
    }
    return p * x;
}

__device__ float jax_normal_123(int i) {
    const uint32_t k0 = 0u, k1 = 123u;
    const uint32_t k2 = k0 ^ k1 ^ 0x1BD11BDAu;
    uint32_t x0 = k0;
    uint32_t x1 = (uint32_t)i + k1;

    #pragma unroll
    for (int r = 0; r < 4; r++) { const uint32_t ra[4] = {13,15,26,6};
        x0 += x1; x1 = rotl32(x1, ra[r]); x1 ^= x0; }
    x0 += k1; x1 += k2 + 1u;
    #pragma unroll
    for (int r = 0; r < 4; r++) { const uint32_t rb[4] = {17,29,16,24};
        x0 += x1; x1 = rotl32(x1, rb[r]); x1 ^= x0; }
    x0 += k2; x1 += k0 + 2u;
    #pragma unroll
    for (int r = 0; r < 4; r++) { const uint32_t ra[4] = {13,15,26,6};
        x0 += x1; x1 = rotl32(x1, ra[r]); x1 ^= x0; }
    x0 += k0; x1 += k1 + 3u;
    #pragma unroll
    for (int r = 0; r < 4; r++) { const uint32_t rb[4] = {17,29,16,24};
        x0 += x1; x1 = rotl32(x1, rb[r]); x1 ^= x0; }
    x0 += k1; x1 += k2 + 4u;
    #pragma unroll
    for (int r = 0; r < 4; r++) { const uint32_t ra[4] = {13,15,26,6};
        x0 += x1; x1 = rotl32(x1, ra[r]); x1 ^= x0; }
    x0 += k2; x1 += k0 + 5u;

    uint32_t bits = x0 ^ x1;
    float f = __uint_as_float((bits >> 9) | 0x3f800000u) - 1.0f;
    const float lo = -0.99999994f;
    float scale = __fsub_rn(1.0f, lo);
    float u = __fadd_rn(__fmul_rn(f, scale), lo);
    u = fmaxf(lo, u);
    return 1.41421356237f * erfinv_xla(u);
}

// ---------------- helpers ----------------
__device__ __forceinline__ float block_excl_scan(float v, int tid, int nthreads, float* ws) {
    __syncthreads();
    int lane = tid & 31, w = tid >> 5, nw = nthreads >> 5;
    float x = v;
    #pragma unroll
    for (int o = 1; o < 32; o <<= 1) {
        float y = __shfl_up_sync(0xffffffffu, x, o);
        if (lane >= o) x += y;
    }
    if (lane == 31) ws[w] = x;
    __syncthreads();
    if (w == 0) {
        float s = (lane < nw) ? ws[lane] : 0.f;
        float xs = s;
        #pragma unroll
        for (int o = 1; o < 32; o <<= 1) {
            float y = __shfl_up_sync(0xffffffffu, xs, o);
            if (lane >= o) xs += y;
        }
        if (lane < nw) ws[lane] = xs - s;
    }
    __syncthreads();
    return ws[w] + (x - v);
}

__device__ __forceinline__ void cp16(uint32_t dst, const void* src) {
    asm volatile("cp.async.cg.shared.global [%0], [%1], 16;" :: "r"(dst), "l"(src));
}

// ---------------- kernel 0: fused setup (prep + wt + cvt_key) ----------------
// blocks [0,64): prep; [64,576): weight transpose; [576,8576): key convert. 512 thr.
__global__ void setup_kernel(const float* __restrict__ key,
                             const float* __restrict__ query,
                             const float* __restrict__ wqm, const float* __restrict__ bkm,
                             const float* __restrict__ wqc, const float* __restrict__ bkc,
                             const float* __restrict__ vmono, const float* __restrict__ gmono,
                             const float* __restrict__ wkm, const float* __restrict__ wkc,
                             float* __restrict__ out_cv) {
    int blk = blockIdx.x, tid = threadIdx.x;
    if (blk < 64) {
        if (blk < 32) {
            int mat = blk >> 4, b = blk & 15;
            const float* wq   = mat ? wqc : wqm;
            const float* bias = mat ? bkc : bkm;
            const float* q = query + b * DD;
            float s = bias[tid];
            for (int k = 0; k < DD; k++) s = fmaf(q[k], wq[k * DD + tid], s);
            if (mat) g_qb_chunk[b][tid] = s; else g_qb_mono[b][tid] = s;
        } else if (blk == 32) {
            __shared__ float red[512];
            float v = vmono[tid];
            red[tid] = v * v;
            __syncthreads();
            for (int off = 256; off > 0; off >>= 1) {
                if (tid < off) red[tid] += red[tid + off];
                __syncthreads();
            }
            float nrm = sqrtf(red[0]);
            g_vm[tid] = gmono[0] * vmono[tid] / nrm;
        } else {
            int nb = 31, bi = blk - 33;
            for (int i = bi * 512 + tid; i < 2 * BT; i += nb * 512) {
                if (i < BT) g_emono[i] = 0.f; else g_echunk[i - BT] = 0.f;
            }
            for (int i = bi * 512 + tid; i < BB * DD; i += nb * 512) out_cv[i] = 0.f;
        }
    } else if (blk < 576) {
        __shared__ float tile[32][33];
        int wb = blk - 64;
        int z = wb >> 8;
        int rem = wb & 255;
        int k0 = (rem >> 4) * 32, n0 = (rem & 15) * 32;
        const float* W = z ? wkc : wkm;
        int tx = tid & 31, ty = tid >> 5;   // ty 0..15
        for (int r = ty; r < 32; r += 16)
            tile[r][tx] = W[(size_t)(k0 + r) * DD + n0 + tx];
        __syncthreads();
        __half* dst = g_wth[z];
        for (int r = ty; r < 32; r += 16)
            dst[(size_t)(n0 + r) * DD + k0 + tx] = __float2half_rn(tile[tx][r]);
    } else {
        size_t i = ((size_t)(blk - 576) * 512 + tid) * 8;
        float4 v0 = *(const float4*)(key + i);
        float4 v1 = *(const float4*)(key + i + 4);
        __half2 h0 = __floats2half2_rn(fmaxf(v0.x, 0.f), fmaxf(v0.y, 0.f));
        __half2 h1 = __floats2half2_rn(fmaxf(v0.z, 0.f), fmaxf(v0.w, 0.f));
        __half2 h2 = __floats2half2_rn(fmaxf(v1.x, 0.f), fmaxf(v1.y, 0.f));
        __half2 h3 = __floats2half2_rn(fmaxf(v1.z, 0.f), fmaxf(v1.w, 0.f));
        uint4 o;
        o.x = *(uint32_t*)&h0; o.y = *(uint32_t*)&h1;
        o.z = *(uint32_t*)&h2; o.w = *(uint32_t*)&h3;
        *(uint4*)(g_keyh + i) = o;
    }
}

// ---------------- kernel 1: fused energy GEMM (fp16 MMA, hoisted XOR addressing) ----------------
__device__ __forceinline__ void mma_f16(float* c, const uint32_t* a, uint32_t b0, uint32_t b1) {
    asm volatile(
        "mma.sync.aligned.m16n8k16.row.col.f32.f16.f16.f32 "
        "{%0,%1,%2,%3}, {%4,%5,%6,%7}, {%8,%9}, {%0,%1,%2,%3};\n"
        : "+f"(c[0]), "+f"(c[1]), "+f"(c[2]), "+f"(c[3])
        : "r"(a[0]), "r"(a[1]), "r"(a[2]), "r"(a[3]), "r"(b0), "r"(b1));
}

__device__ __forceinline__ void ldsm4(uint32_t* r, uint32_t addr) {
    asm volatile("ldmatrix.sync.aligned.m8n8.x4.shared.b16 {%0,%1,%2,%3}, [%4];"
        : "=r"(r[0]), "=r"(r[1]), "=r"(r[2]), "=r"(r[3]) : "r"(addr));
}

#define A_BYTES 16384                     // 128 rows x 128B (64 halves)
#define STAGE_BYTES 32768                 // A + B
#define NSTAGE 3
#define EK_SMEM (NSTAGE * STAGE_BYTES)    // 96 KB

// grid (8 colchunks, 500 rowblocks), 256 threads (8 warps: 4 M x 2 N)
__global__ __launch_bounds__(256, 2) void energy_kernel(const float* __restrict__ vchunk) {
    extern __shared__ __align__(128) char smem[];

    int tid  = threadIdx.x;
    int lane = tid & 31, wid = tid >> 5;
    int g = lane >> 2, q = lane & 3;
    int lmrow = lane & 7, lmm = lane >> 3;
    int warp_m = wid & 3, warp_n = wid >> 2;
    int row0 = blockIdx.y * 128;
    int cc = blockIdx.x;
    int mat = cc >> 2;
    int a0 = (cc & 3) * 128;
    const __half* Wt = g_wth[mat];

    uint32_t sbase = (uint32_t)__cvta_generic_to_shared(smem);

    // ---- hoisted ldmatrix offsets: addr = (stagebase + pre [+16384 for B]) ^ (ks*32)
    // pre = row*128 + (lmrow*16 ^ h16), h16 = (lmm>>1)*16; rows differ by +16 -> +2048
    int h16 = (lmm >> 1) << 4;
    int rA = warp_m * 32 + ((lmm & 1) << 3) + lmrow;
    int rB = warp_n * 64 + ((lmm & 1) << 3) + lmrow;
    uint32_t preA = (uint32_t)(rA * 128 + ((lmrow << 4) ^ h16));
    uint32_t preB = (uint32_t)(rB * 128 + ((lmrow << 4) ^ h16)) + A_BYTES;

    // ---- hoisted cp.async destinations: (m&7)==(cm&7) for all p
    int cm = tid >> 3, cck = tid & 7;
    uint32_t dA = (uint32_t)(cm * 128 + ((cck ^ (cm & 7)) << 4));
    uint32_t dB = dA + A_BYTES;
    const char* srcA = (const char*)(g_keyh + (size_t)(row0 + cm) * 512) + cck * 16;
    const char* srcB = (const char*)(Wt + (size_t)(a0 + cm) * 512) + cck * 16;

    float acc[2][8][4];
    #pragma unroll
    for (int mi = 0; mi < 2; mi++)
        #pragma unroll
        for (int ni = 0; ni < 8; ni++)
            #pragma unroll
            for (int x = 0; x < 4; x++) acc[mi][ni][x] = 0.f;

    #define PREFETCH(kb, st) do {                                               \
        uint32_t sb = sbase + (uint32_t)((st) * STAGE_BYTES);                   \
        const char* sa = srcA + (size_t)(kb) * 128;                             \
        const char* sbp = srcB + (size_t)(kb) * 128;                            \
        _Pragma("unroll")                                                       \
        for (int p = 0; p < 4; p++)                                             \
            cp16(sb + dA + (uint32_t)(p * 4096), sa + (size_t)p * 32768);       \
        _Pragma("unroll")                                                       \
        for (int p = 0; p < 4; p++)                                             \
            cp16(sb + dB + (uint32_t)(p * 4096), sbp + (size_t)p * 32768);      \
        asm volatile("cp.async.commit_group;");                                 \
    } while (0)

    PREFETCH(0, 0);
    PREFETCH(1, 1);

    int scur = 0;
    for (int kb = 0; kb < 8; kb++) {
        if (kb + 1 < 8) asm volatile("cp.async.wait_group 1;");
        else            asm volatile("cp.async.wait_group 0;");
        __syncthreads();

        if (kb + 2 < 8) {
            int spre = (scur == 0) ? 2 : scur - 1;
            PREFETCH(kb + 2, spre);
        }

        uint32_t stb = sbase + (uint32_t)(scur * STAGE_BYTES);
        uint32_t aS = stb + preA;
        uint32_t bS = stb + preB;
        #pragma unroll
        for (int ks = 0; ks < 4; ks++) {
            const uint32_t kx = (uint32_t)(ks * 32);
            uint32_t afr[2][4];
            ldsm4(afr[0], aS ^ kx);
            ldsm4(afr[1], (aS + 2048) ^ kx);
            uint32_t bfr[4][4];
            #pragma unroll
            for (int nb = 0; nb < 4; nb++)
                ldsm4(bfr[nb], (bS + (uint32_t)(nb * 2048)) ^ kx);
            #pragma unroll
            for (int nb = 0; nb < 4; nb++) {
                mma_f16(acc[0][nb * 2    ], afr[0], bfr[nb][0], bfr[nb][2]);
                mma_f16(acc[0][nb * 2 + 1], afr[0], bfr[nb][1], bfr[nb][3]);
                mma_f16(acc[1][nb * 2    ], afr[1], bfr[nb][0], bfr[nb][2]);
                mma_f16(acc[1][nb * 2 + 1], afr[1], bfr[nb][1], bfr[nb][3]);
            }
        }
        scur = (scur == 2) ? 0 : scur + 1;
    }
    __syncthreads();

    // epilogue: e_partial(row) = sum_a tanh(acc + qb[b][a]) * v[a]
    const float* qbp = mat ? &g_qb_chunk[0][0] : &g_qb_mono[0][0];
    const float* vp  = mat ? vchunk : g_vm;
    float* eout      = mat ? g_echunk : g_emono;
    float (*red)[9]  = (float(*)[9])smem;

    #pragma unroll
    for (int mi = 0; mi < 2; mi++) {
        #pragma unroll
        for (int half = 0; half < 2; half++) {
            int lr = warp_m * 32 + mi * 16 + half * 8 + g;
            int b  = (row0 + lr) / TT;
            const float* qb = qbp + b * DD + a0;
            float s = 0.f;
            #pragma unroll
            for (int ni = 0; ni < 8; ni++) {
                int n = warp_n * 64 + ni * 8 + 2 * q;
                float c0 = acc[mi][ni][half * 2 + 0];
                float c1 = acc[mi][ni][half * 2 + 1];
                s = fmaf(tanhf(c0 + qb[n]),     vp[a0 + n],     s);
                s = fmaf(tanhf(c1 + qb[n + 1]), vp[a0 + n + 1], s);
            }
            red[lr][warp_n * 4 + q] = s;
        }
    }
    __syncthreads();
    if (tid < 128) {
        float s = 0.f;
        #pragma unroll
        for (int x = 0; x < 8; x++) s += red[tid][x];
        atomicAdd(&eout[row0 + tid], s);
    }
    #undef PREFETCH
}

// ---------------- kernel 2: fused scans (mono alpha + chunk beta) ----------------
// 16 blocks x 512 threads; dynamic smem 64000B: A1,A2,A3,A4 [4000] each
__global__ void scan_fused_kernel(const int* __restrict__ mask,
                                  const float* __restrict__ rmono,
                                  float* __restrict__ out_alpha) {
    extern __shared__ float sm[];
    float* A1 = sm;            // lp, then se
    float* A2 = sm + 4000;     // pp, then alpha
    float* A3 = sm + 8000;     // pref
    float* A4 = sm + 12000;    // qp
    __shared__ float sh[512];

    int b = blockIdx.x, tid = threadIdx.x;
    const int CH = 8;
    int t0 = tid * CH, t1 = min(t0 + CH, TT);

    // ---- phase 1: mono -> alpha (in A2) + out_alpha
    {
        float r = rmono[0];
        float s = 0.f;
        for (int t = t0; t < t1; t++) {
            int i = b * TT + t;
            float e = g_emono[i] + r;
            if (mask[i] == 0) e = NEG_INF;
            float x = e + jax_normal_123(i);
            float p = 1.f / (1.f + expf(-x));
            float l = logf(fminf(fmaxf(1.f - p, EPSF), 1.f));
            A2[t] = p; A1[t] = l; s += l;
        }
        float run = block_excl_scan(s, tid, 512, sh);
        for (int t = t0; t < t1; t++) {
            float al = A2[t] * expf(run);
            run += A1[t];
            A2[t] = al;
            out_alpha[b * TT + t] = al;
        }
    }
    __syncthreads();

    // ---- phase 2: chunk energies -> beta
    float mx = -3.4e38f;
    for (int t = tid; t < TT; t += 512) {
        float e = g_echunk[b * TT + t];
        if (mask[b * TT + t] == 0) e = NEG_INF;
        A1[t] = e;
        mx = fmaxf(mx, e);
    }
    sh[tid] = mx;
    __syncthreads();
    for (int off = 256; off > 0; off >>= 1) {
        if (tid < off) sh[tid] = fmaxf(sh[tid], sh[tid + off]);
        __syncthreads();
    }
    mx = sh[0];
    __syncthreads();

    for (int t = tid; t < TT; t += 512) A1[t] = fmaxf(expf(A1[t] - mx), 1e-5f);
    __syncthreads();
    {
        float s = 0.f;
        for (int t = t0; t < t1; t++) s += A1[t];
        float run = block_excl_scan(s, tid, 512, sh);
        for (int t = t0; t < t1; t++) { run += A1[t]; A3[t] = run; }
    }
    __syncthreads();

    for (int t = tid; t < TT; t += 512) {
        float denom = A3[t] - ((t >= 8) ? A3[t - 8] : 0.f);
        A4[t] = A2[t] / denom;
    }
    __syncthreads();

    {
        float s = 0.f;
        for (int t = t0; t < t1; t++) s += A4[t];
        float run = block_excl_scan(s, tid, 512, sh);
        for (int t = t0; t < t1; t++) { run += A4[t]; A4[t] = run; }
    }
    __syncthreads();

    for (int t = tid; t < TT; t += 512) {
        int hi = min(t + 7, TT - 1);
        float ms2 = A4[hi] - ((t > 0) ? A4[t - 1] : 0.f);
        g_beta[b * TT + t] = A1[t] * ms2;
    }
}

// ---------------- kernel 3: cv = sum_t beta * value (beta-sparse skip) ----------------
__global__ void cv_kernel(const float* __restrict__ value, float* __restrict__ out_cv) {
    __shared__ float bsh[125];
    int tc = blockIdx.x;   // 32 chunks of 125
    int b  = blockIdx.y;
    int d  = threadIdx.x;  // 512
    int t0 = tc * 125;
    if (d < 125) bsh[d] = g_beta[b * TT + t0 + d];
    __syncthreads();
    float acc = 0.f;
    bool any = false;
    for (int t = 0; t < 125; t++) {
        float bv = bsh[t];
        if (fabsf(bv) > 1e-14f) {   // uniform branch; dropped mass < 1e-9 abs
            acc = fmaf(bv, value[(size_t)(b * TT + t0 + t) * 512 + d], acc);
            any = true;
        }
    }
    if (any) atomicAdd(&out_cv[b * 512 + d], acc);
}

// ---------------- launch ----------------
extern "C" void kernel_launch(void* const* d_in, const int* in_sizes, int n_in,
                              void* d_out, int out_size) {
    const float* key    = (const float*)d_in[0];
    const float* value  = (const float*)d_in[1];
    const float* query  = (const float*)d_in[2];
    const int*   mask   = (const int*)  d_in[3];
    const float* wkm    = (const float*)d_in[4];
    const float* bkm    = (const float*)d_in[5];
    const float* wqm    = (const float*)d_in[6];
    const float* vmono  = (const float*)d_in[7];
    const float* gmono  = (const float*)d_in[8];
    const float* rmono  = (const float*)d_in[9];
    const float* wkc    = (const float*)d_in[10];
    const float* bkc    = (const float*)d_in[11];
    const float* wqc    = (const float*)d_in[12];
    const float* vchunk = (const float*)d_in[13];

    float* out       = (float*)d_out;
    float* out_cv    = out;            // [16, 1, 512] first
    float* out_alpha = out + BB * DD;  // [16, 4000, 1] second

    cudaFuncSetAttribute(energy_kernel, cudaFuncAttributeMaxDynamicSharedMemorySize, EK_SMEM);
    cudaFuncSetAttribute(scan_fused_kernel, cudaFuncAttributeMaxDynamicSharedMemorySize, 64000);

    setup_kernel<<<8576, 512>>>(key, query, wqm, bkm, wqc, bkc, vmono, gmono,
                                wkm, wkc, out_cv);
    energy_kernel<<<dim3(8, 500), 256, EK_SMEM>>>(vchunk);
    scan_fused_kernel<<<16, 512, 64000>>>(mask, rmono, out_alpha);
    cv_kernel<<<dim3(32, 16), 512>>>(value, out_cv);
}